// round 2
// baseline (speedup 1.0000x reference)
#include <cuda_runtime.h>
#include <cstdint>
#include <cstddef>

// ---------------------------------------------------------------------------
// PhysicsInformedAttention — GB300 baseline (fp32, physics biases cancel)
//
// Shapes: B=2, S=2048, HIDDEN=1024, NH=16, D=64, SA=S+3=2051
// dir 0: queries = aug(cnn), kv = aug(llm);  dir 1: queries = aug(llm), kv = aug(cnn)
// out = concat(LN(cnn + attn0 @ Wo + bo), LN(llm + attn1 @ Wo + bo))
// ---------------------------------------------------------------------------

#define Bz 2
#define SEQ 2048
#define SA 2051
#define HID 1024
#define NHEADS 16
#define HD 64

// Scratch (static device allocations — no cudaMalloc allowed)
__device__ float g_aug[2 * Bz * SA * HID];   // [src][b][sa][H]
__device__ float g_Q  [2 * Bz * SA * HID];   // Q of each src (extra 3 rows unused)
__device__ float g_K  [2 * Bz * SA * HID];
__device__ float g_V  [2 * Bz * SA * HID];
__device__ float g_att[2 * Bz * SEQ * HID];  // attended, per dir
__device__ float g_O  [2 * Bz * SEQ * HID];  // O-projection, per dir

// ---------------------------------------------------------------------------
// Kernel 1: build augmented tensors: aug[src] = concat(features, e, m, p)
// ---------------------------------------------------------------------------
__global__ __launch_bounds__(256) void build_aug(
    const float* __restrict__ cnn, const float* __restrict__ llm,
    const float* __restrict__ ee, const float* __restrict__ me,
    const float* __restrict__ pe)
{
    int row = blockIdx.x;                 // 0 .. 2*Bz*SA-1
    int src = row / (Bz * SA);
    int rem = row - src * (Bz * SA);
    int b   = rem / SA;
    int s   = rem - b * SA;
    const float* p;
    if (s < SEQ) p = (src ? llm : cnn) + ((size_t)(b * SEQ + s)) * HID;
    else         p = (s == SEQ ? ee : (s == SEQ + 1 ? me : pe));
    float* dst = g_aug + (size_t)row * HID;
    int t = threadIdx.x;
    *(float4*)(dst + t * 4) = *(const float4*)(p + t * 4);
}

// ---------------------------------------------------------------------------
// SGEMM body: C[M,1024] = A[M,1024] @ W[1024,1024] + bias, 128x128x8 tiles
// ---------------------------------------------------------------------------
__device__ __forceinline__ void sgemm_body(
    const float* __restrict__ A, const float* __restrict__ W,
    const float* __restrict__ bias, float* __restrict__ C, int M)
{
    constexpr int N = 1024, K = 1024;
    __shared__ float As[8][128];
    __shared__ float Bs[8][128];

    const int tid = threadIdx.x;                // 256
    const int bx = blockIdx.x;                  // N / 128
    const int by = blockIdx.y;                  // ceil(M/128)
    const int tr = tid >> 4;                    // 0..15
    const int tc = tid & 15;                    // 0..15
    const int arow = tid >> 1;                  // 0..127
    const int acol = (tid & 1) << 2;            // 0 or 4
    const int brow = tid >> 5;                  // 0..7
    const int bcol = (tid & 31) << 2;           // 0..124

    const int agr = by * 128 + arow;
    const bool avalid = agr < M;
    const float* Aptr = A + (size_t)agr * K + acol;
    const float* Wptr = W + (size_t)brow * N + bx * 128 + bcol;

    float acc[8][8];
#pragma unroll
    for (int i = 0; i < 8; i++)
#pragma unroll
        for (int j = 0; j < 8; j++) acc[i][j] = 0.f;

    for (int k0 = 0; k0 < K; k0 += 8) {
        float4 av = avalid ? *(const float4*)(Aptr + k0) : make_float4(0, 0, 0, 0);
        float4 bv = *(const float4*)(Wptr + (size_t)k0 * N);
        As[acol + 0][arow] = av.x;
        As[acol + 1][arow] = av.y;
        As[acol + 2][arow] = av.z;
        As[acol + 3][arow] = av.w;
        *(float4*)&Bs[brow][bcol] = bv;
        __syncthreads();
#pragma unroll
        for (int kk = 0; kk < 8; kk++) {
            float a[8], bb[8];
            *(float4*)&a[0] = *(const float4*)&As[kk][tr * 8];
            *(float4*)&a[4] = *(const float4*)&As[kk][tr * 8 + 4];
            *(float4*)&bb[0] = *(const float4*)&Bs[kk][tc * 8];
            *(float4*)&bb[4] = *(const float4*)&Bs[kk][tc * 8 + 4];
#pragma unroll
            for (int i = 0; i < 8; i++)
#pragma unroll
                for (int j = 0; j < 8; j++)
                    acc[i][j] = fmaf(a[i], bb[j], acc[i][j]);
        }
        __syncthreads();
    }

    const int gc = bx * 128 + tc * 8;
#pragma unroll
    for (int i = 0; i < 8; i++) {
        int gr = by * 128 + tr * 8 + i;
        if (gr < M) {
            float* cp = C + (size_t)gr * N + gc;
            float4 v0, v1;
            v0.x = acc[i][0] + bias[gc + 0];
            v0.y = acc[i][1] + bias[gc + 1];
            v0.z = acc[i][2] + bias[gc + 2];
            v0.w = acc[i][3] + bias[gc + 3];
            v1.x = acc[i][4] + bias[gc + 4];
            v1.y = acc[i][5] + bias[gc + 5];
            v1.z = acc[i][6] + bias[gc + 6];
            v1.w = acc[i][7] + bias[gc + 7];
            *(float4*)(cp + 0) = v0;
            *(float4*)(cp + 4) = v1;
        }
    }
}

// QKV projections for both sources: grid.z = src*3 + {Q,K,V}
__global__ __launch_bounds__(256, 2) void qkv_gemm(
    const float* __restrict__ Wq, const float* __restrict__ bq,
    const float* __restrict__ Wk, const float* __restrict__ bk,
    const float* __restrict__ Wv, const float* __restrict__ bv)
{
    int z = blockIdx.z;
    int src = z / 3, w = z - src * 3;
    const float* A = g_aug + (size_t)src * (Bz * SA * HID);
    const float* Wp; const float* bp; float* C;
    if (w == 0)      { Wp = Wq; bp = bq; C = g_Q; }
    else if (w == 1) { Wp = Wk; bp = bk; C = g_K; }
    else             { Wp = Wv; bp = bv; C = g_V; }
    C += (size_t)src * (Bz * SA * HID);
    sgemm_body(A, Wp, bp, C, Bz * SA);
}

// O projection for both directions: grid.z = dir
__global__ __launch_bounds__(256, 2) void oproj_gemm(
    const float* __restrict__ Wo, const float* __restrict__ bo)
{
    int dir = blockIdx.z;
    sgemm_body(g_att + (size_t)dir * (Bz * SEQ * HID), Wo, bo,
               g_O + (size_t)dir * (Bz * SEQ * HID), Bz * SEQ);
}

// ---------------------------------------------------------------------------
// Kernel 3: flash-style attention (per-row softmax bias cancels; scores are
// tiny so no max-subtraction is needed — exact softmax up to fp rounding).
// grid: (S/128, NH, 2*Bz); 128 threads, one query row per thread.
// ---------------------------------------------------------------------------
__global__ __launch_bounds__(128) void attn_kernel()
{
    const int qt = blockIdx.x;
    const int h  = blockIdx.y;
    const int dir = blockIdx.z >> 1;
    const int b   = blockIdx.z & 1;
    const int qsrc = dir;
    const int ksrc = dir ^ 1;
    const int tid = threadIdx.x;
    const int qrow = qt * 128 + tid;

    __shared__ float Ks[64][64];
    __shared__ float Vs[64][64];

    float q[64], o[64];
    const float* qptr = g_Q + ((size_t)((qsrc * Bz + b) * SA + qrow)) * HID + h * HD;
#pragma unroll
    for (int i = 0; i < 16; i++) {
        float4 v = *(const float4*)(qptr + i * 4);
        q[i * 4 + 0] = v.x; q[i * 4 + 1] = v.y; q[i * 4 + 2] = v.z; q[i * 4 + 3] = v.w;
    }
#pragma unroll
    for (int d = 0; d < 64; d++) o[d] = 0.f;
    float l = 0.f;

    const int r  = tid >> 1;
    const int c0 = (tid & 1) * 32;
    const size_t kvbase = ((size_t)((ksrc * Bz + b) * SA)) * HID + h * HD;

    for (int kt = 0; kt < (SA + 63) / 64; kt++) {
        int kb = kt * 64;
        int kn = min(64, SA - kb);
        if (r < kn) {
            const float* kp = g_K + kvbase + (size_t)(kb + r) * HID + c0;
            const float* vp = g_V + kvbase + (size_t)(kb + r) * HID + c0;
#pragma unroll
            for (int i = 0; i < 8; i++) {
                *(float4*)&Ks[r][c0 + i * 4] = *(const float4*)(kp + i * 4);
                *(float4*)&Vs[r][c0 + i * 4] = *(const float4*)(vp + i * 4);
            }
        }
        __syncthreads();

        for (int j = 0; j < kn; j++) {
            float a0 = 0.f, a1 = 0.f, a2 = 0.f, a3 = 0.f;
#pragma unroll
            for (int i = 0; i < 16; i++) {
                float4 kv = *(const float4*)&Ks[j][i * 4];
                a0 = fmaf(q[i * 4 + 0], kv.x, a0);
                a1 = fmaf(q[i * 4 + 1], kv.y, a1);
                a2 = fmaf(q[i * 4 + 2], kv.z, a2);
                a3 = fmaf(q[i * 4 + 3], kv.w, a3);
            }
            float s = (a0 + a1) + (a2 + a3);
            float p = __expf(s * 0.125f);   // 1/sqrt(64); no max needed (|s| small)
            l += p;
#pragma unroll
            for (int i = 0; i < 16; i++) {
                float4 vv = *(const float4*)&Vs[j][i * 4];
                o[i * 4 + 0] = fmaf(p, vv.x, o[i * 4 + 0]);
                o[i * 4 + 1] = fmaf(p, vv.y, o[i * 4 + 1]);
                o[i * 4 + 2] = fmaf(p, vv.z, o[i * 4 + 2]);
                o[i * 4 + 3] = fmaf(p, vv.w, o[i * 4 + 3]);
            }
        }
        __syncthreads();
    }

    float inv = 1.0f / l;
    float* outp = g_att + ((size_t)((dir * Bz + b) * SEQ + qrow)) * HID + h * HD;
#pragma unroll
    for (int i = 0; i < 16; i++) {
        float4 v;
        v.x = o[i * 4 + 0] * inv;
        v.y = o[i * 4 + 1] * inv;
        v.z = o[i * 4 + 2] * inv;
        v.w = o[i * 4 + 3] * inv;
        *(float4*)(outp + i * 4) = v;
    }
}

// ---------------------------------------------------------------------------
// Kernel 4: residual + LayerNorm, writes final output
// grid: 2*Bz*SEQ rows, 256 threads (4 elems each)
// ---------------------------------------------------------------------------
__global__ __launch_bounds__(256) void resid_ln(
    const float* __restrict__ cnn, const float* __restrict__ llm,
    const float* __restrict__ gamma, const float* __restrict__ beta,
    float* __restrict__ out)
{
    int row = blockIdx.x;               // (dir*Bz + b)*SEQ + s
    int dir = row >> 12;                // 4096 rows per dir
    int b   = (row >> 11) & 1;
    int s   = row & (SEQ - 1);
    const float* resid = (dir ? llm : cnn) + ((size_t)(b * SEQ + s)) * HID;
    const float* op = g_O + (size_t)row * HID;
    int t = threadIdx.x;

    float4 rv = *(const float4*)(resid + t * 4);
    float4 ov = *(const float4*)(op + t * 4);
    float x0 = rv.x + ov.x, x1 = rv.y + ov.y, x2 = rv.z + ov.z, x3 = rv.w + ov.w;
    float s1 = (x0 + x1) + (x2 + x3);
    float s2 = x0 * x0 + x1 * x1 + x2 * x2 + x3 * x3;
#pragma unroll
    for (int off = 16; off; off >>= 1) {
        s1 += __shfl_xor_sync(0xFFFFFFFFu, s1, off);
        s2 += __shfl_xor_sync(0xFFFFFFFFu, s2, off);
    }
    __shared__ float sm1[8], sm2[8];
    int warp = t >> 5, lane = t & 31;
    if (lane == 0) { sm1[warp] = s1; sm2[warp] = s2; }
    __syncthreads();
    if (t == 0) {
        float a = 0.f, c = 0.f;
#pragma unroll
        for (int i = 0; i < 8; i++) { a += sm1[i]; c += sm2[i]; }
        sm1[0] = a; sm2[0] = c;
    }
    __syncthreads();
    float mean = sm1[0] * (1.0f / HID);
    float var  = sm2[0] * (1.0f / HID) - mean * mean;
    float rstd = rsqrtf(var + 1e-5f);

    float4 g = *(const float4*)(gamma + t * 4);
    float4 be = *(const float4*)(beta + t * 4);
    float4 y;
    y.x = (x0 - mean) * rstd * g.x + be.x;
    y.y = (x1 - mean) * rstd * g.y + be.y;
    y.z = (x2 - mean) * rstd * g.z + be.z;
    y.w = (x3 - mean) * rstd * g.w + be.w;
    *(float4*)(out + (size_t)row * HID + t * 4) = y;
}

// ---------------------------------------------------------------------------
extern "C" void kernel_launch(void* const* d_in, const int* in_sizes, int n_in,
                              void* d_out, int out_size)
{
    const float* cnn = (const float*)d_in[0];
    const float* llm = (const float*)d_in[1];
    const float* Wq  = (const float*)d_in[2];
    const float* bq  = (const float*)d_in[3];
    const float* Wk  = (const float*)d_in[4];
    const float* bk  = (const float*)d_in[5];
    const float* Wv  = (const float*)d_in[6];
    const float* bv  = (const float*)d_in[7];
    const float* Wo  = (const float*)d_in[8];
    const float* bo  = (const float*)d_in[9];
    const float* ee  = (const float*)d_in[10];
    const float* me  = (const float*)d_in[11];
    const float* pe  = (const float*)d_in[12];
    const float* gamma = (const float*)d_in[13];
    const float* beta  = (const float*)d_in[14];
    float* out = (float*)d_out;

    // 1. Build augmented K/V source tensors
    build_aug<<<2 * Bz * SA, 256>>>(cnn, llm, ee, me, pe);

    // 2. Q/K/V projections for both sources (6 GEMMs in one launch)
    {
        dim3 grid(HID / 128, (Bz * SA + 127) / 128, 6);
        qkv_gemm<<<grid, 256>>>(Wq, bq, Wk, bk, Wv, bv);
    }

    // 3. Cross-attention, both directions
    {
        dim3 grid(SEQ / 128, NHEADS, 2 * Bz);
        attn_kernel<<<grid, 128>>>();
    }

    // 4. Output projection (2 GEMMs in one launch)
    {
        dim3 grid(HID / 128, (Bz * SEQ) / 128, 2);
        oproj_gemm<<<grid, 256>>>(Wo, bo);
    }

    // 5. Residual + LayerNorm -> final output
    resid_ln<<<2 * Bz * SEQ, 256>>>(cnn, llm, gamma, beta, out);
}

// round 5
// speedup vs baseline: 3.8087x; 3.8087x over previous
#include <cuda_runtime.h>
#include <cstdint>
#include <cstddef>

// ---------------------------------------------------------------------------
// PhysicsInformedAttention — Round 3: tf32 mma.sync everywhere
// B=2, S=2048, HIDDEN=1024, NH=16, D=64, SA=2051. Physics biases cancel in
// softmax (per-row constants) -> plain cross-attention. fp32 accumulate.
// ---------------------------------------------------------------------------

#define Bz 2
#define SEQ 2048
#define SA 2051
#define HID 1024
#define NHEADS 16
#define HD 64

__device__ float g_aug[2 * Bz * SA * HID];
__device__ float g_Q  [2 * Bz * SA * HID];
__device__ float g_K  [2 * Bz * SA * HID];
__device__ float g_V  [2 * Bz * SA * HID];
__device__ float g_att[2 * Bz * SEQ * HID];
__device__ float g_O  [2 * Bz * SEQ * HID];

// ----------------------------- helpers -------------------------------------
__device__ __forceinline__ float f2tf(float x) {
    uint32_t u;
    asm("cvt.rna.tf32.f32 %0, %1;" : "=r"(u) : "f"(x));
    return __uint_as_float(u);
}
__device__ __forceinline__ uint32_t fbits(float x) { return __float_as_uint(x); }

__device__ __forceinline__ void mma_tf32(float* d, const uint32_t* a,
                                         const uint32_t* b, const float* c) {
    asm volatile(
        "mma.sync.aligned.m16n8k8.row.col.f32.tf32.tf32.f32 "
        "{%0,%1,%2,%3}, {%4,%5,%6,%7}, {%8,%9}, {%10,%11,%12,%13};\n"
        : "=f"(d[0]), "=f"(d[1]), "=f"(d[2]), "=f"(d[3])
        : "r"(a[0]), "r"(a[1]), "r"(a[2]), "r"(a[3]),
          "r"(b[0]), "r"(b[1]),
          "f"(c[0]), "f"(c[1]), "f"(c[2]), "f"(c[3]));
}

// ---------------------------------------------------------------------------
// Kernel 1: build augmented tensors
// ---------------------------------------------------------------------------
__global__ __launch_bounds__(256) void build_aug(
    const float* __restrict__ cnn, const float* __restrict__ llm,
    const float* __restrict__ ee, const float* __restrict__ me,
    const float* __restrict__ pe)
{
    int row = blockIdx.x;
    int src = row / (Bz * SA);
    int rem = row - src * (Bz * SA);
    int b   = rem / SA;
    int s   = rem - b * SA;
    const float* p;
    if (s < SEQ) p = (src ? llm : cnn) + ((size_t)(b * SEQ + s)) * HID;
    else         p = (s == SEQ ? ee : (s == SEQ + 1 ? me : pe));
    float* dst = g_aug + (size_t)row * HID;
    int t = threadIdx.x;
    *(float4*)(dst + t * 4) = *(const float4*)(p + t * 4);
}

// ---------------------------------------------------------------------------
// tf32 GEMM body: C[M,1024] = A[M,1024] @ W[1024,1024] + bias
// 128x128 block tile, K-chunk 32, 256 threads = 8 warps (2x4), warp tile 64x32
// ---------------------------------------------------------------------------
__device__ __forceinline__ void gemm_tf32_body(
    const float* __restrict__ A, const float* __restrict__ W,
    const float* __restrict__ bias, float* __restrict__ C, int M)
{
    constexpr int N = 1024, K = 1024;
    __shared__ float As[128][36];   // [m][k], pad 4 -> frag reads conflict-free
    __shared__ float Bs[32][136];   // [k][n], pad 8 -> frag reads conflict-free

    const int tid = threadIdx.x;
    const int lane = tid & 31;
    const int warp = tid >> 5;
    const int q = lane >> 2, r = lane & 3;
    const int wm = warp >> 2;       // 0..1
    const int wn = warp & 3;        // 0..3
    const int bx = blockIdx.x, by = blockIdx.y;

    // A fill: thread -> row=tid/2, col base=(tid&1)*4, 4x float4 at col+8i
    const int ar  = tid >> 1;
    const int ac  = (tid & 1) * 4;
    const int agr = by * 128 + ar;
    const bool aval = agr < M;
    const float* Arow = A + (size_t)agr * K;
    // B fill: thread -> k=tid/8, n base=(tid&7)*4, 4x float4 at n+32i
    const int br = tid >> 3;
    const int bc = (tid & 7) * 4;
    const float* Wbase = W + (size_t)br * N + bx * 128 + bc;

    float4 ap[4], bp[4];
#pragma unroll
    for (int i = 0; i < 4; i++) {
        ap[i] = aval ? *(const float4*)(Arow + ac + 8 * i) : make_float4(0,0,0,0);
        bp[i] = *(const float4*)(Wbase + (size_t)0 * N + 32 * i);
    }

    float acc[16][4];
#pragma unroll
    for (int i = 0; i < 16; i++)
#pragma unroll
        for (int j = 0; j < 4; j++) acc[i][j] = 0.f;

    for (int kb = 0; kb < K; kb += 32) {
        __syncthreads();
#pragma unroll
        for (int i = 0; i < 4; i++) {
            float4 v = ap[i];
            v.x = f2tf(v.x); v.y = f2tf(v.y); v.z = f2tf(v.z); v.w = f2tf(v.w);
            *(float4*)&As[ar][ac + 8 * i] = v;
            float4 w = bp[i];
            w.x = f2tf(w.x); w.y = f2tf(w.y); w.z = f2tf(w.z); w.w = f2tf(w.w);
            *(float4*)&Bs[br][bc + 32 * i] = w;
        }
        __syncthreads();
        if (kb + 32 < K) {
#pragma unroll
            for (int i = 0; i < 4; i++) {
                ap[i] = aval ? *(const float4*)(Arow + kb + 32 + ac + 8 * i)
                             : make_float4(0,0,0,0);
                bp[i] = *(const float4*)(Wbase + (size_t)(kb + 32) * N + 32 * i);
            }
        }
#pragma unroll
        for (int ks = 0; ks < 4; ks++) {
            const int k0 = ks * 8;
            uint32_t af[4][4];
#pragma unroll
            for (int mt = 0; mt < 4; mt++) {
                const int m0 = wm * 64 + mt * 16 + q;
                af[mt][0] = fbits(As[m0    ][k0 + r    ]);
                af[mt][1] = fbits(As[m0 + 8][k0 + r    ]);
                af[mt][2] = fbits(As[m0    ][k0 + r + 4]);
                af[mt][3] = fbits(As[m0 + 8][k0 + r + 4]);
            }
            uint32_t bf[4][2];
#pragma unroll
            for (int nt = 0; nt < 4; nt++) {
                const int n0 = wn * 32 + nt * 8 + q;
                bf[nt][0] = fbits(Bs[k0 + r    ][n0]);
                bf[nt][1] = fbits(Bs[k0 + r + 4][n0]);
            }
#pragma unroll
            for (int mt = 0; mt < 4; mt++)
#pragma unroll
                for (int nt = 0; nt < 4; nt++)
                    mma_tf32(acc[mt * 4 + nt], af[mt], bf[nt], acc[mt * 4 + nt]);
        }
    }

    // epilogue
#pragma unroll
    for (int mt = 0; mt < 4; mt++) {
#pragma unroll
        for (int nt = 0; nt < 4; nt++) {
            const int row0 = by * 128 + wm * 64 + mt * 16 + q;
            const int col  = bx * 128 + wn * 32 + nt * 8 + 2 * r;
            const float b0 = bias[col], b1 = bias[col + 1];
            const float* a = acc[mt * 4 + nt];
            if (row0 < M) {
                float2 v = make_float2(a[0] + b0, a[1] + b1);
                *(float2*)(C + (size_t)row0 * N + col) = v;
            }
            if (row0 + 8 < M) {
                float2 v = make_float2(a[2] + b0, a[3] + b1);
                *(float2*)(C + (size_t)(row0 + 8) * N + col) = v;
            }
        }
    }
}

__global__ __launch_bounds__(256, 2) void qkv_gemm(
    const float* __restrict__ Wq, const float* __restrict__ bq,
    const float* __restrict__ Wk, const float* __restrict__ bk,
    const float* __restrict__ Wv, const float* __restrict__ bv)
{
    int z = blockIdx.z;
    int src = z / 3, w = z - src * 3;
    const float* A = g_aug + (size_t)src * (Bz * SA * HID);
    const float* Wp; const float* bp; float* C;
    if (w == 0)      { Wp = Wq; bp = bq; C = g_Q; }
    else if (w == 1) { Wp = Wk; bp = bk; C = g_K; }
    else             { Wp = Wv; bp = bv; C = g_V; }
    C += (size_t)src * (Bz * SA * HID);
    gemm_tf32_body(A, Wp, bp, C, Bz * SA);
}

__global__ __launch_bounds__(256, 2) void oproj_gemm(
    const float* __restrict__ Wo, const float* __restrict__ bo)
{
    int dir = blockIdx.z;
    gemm_tf32_body(g_att + (size_t)dir * (Bz * SEQ * HID), Wo, bo,
                   g_O + (size_t)dir * (Bz * SEQ * HID), Bz * SEQ);
}

// ---------------------------------------------------------------------------
// Flash attention with tf32 mma. 256 threads = 8 warps; each warp owns 16 full
// q-rows (all key/d columns) so softmax needs only quad shuffles.
// Block tile: 128 q-rows, Bc=32 keys/iter, D=64.
// ---------------------------------------------------------------------------
__global__ __launch_bounds__(256, 2) void attn_tf32()
{
    __shared__ float Ps[128][36];   // P tile (also Q staging, 32-col halves)
    __shared__ float Ks[32][68];    // [key][d]
    __shared__ float Vs[32][68];    // [key][d]

    const int tid = threadIdx.x;
    const int lane = tid & 31;
    const int warp = tid >> 5;       // 0..7, owns q rows [16w,16w+16)
    const int q = lane >> 2, r = lane & 3;

    const int qt  = blockIdx.x;      // 16 q-tiles
    const int h   = blockIdx.y;      // head
    const int dir = blockIdx.z >> 1;
    const int b   = blockIdx.z & 1;

    const size_t qbase  = ((size_t)((dir * Bz + b) * SA) + qt * 128) * HID + h * HD;
    const size_t kvbase = ((size_t)(((dir ^ 1) * Bz + b) * SA)) * HID + h * HD;

    // ---- load Q A-fragments (persistent), staged through Ps in 2 halves ----
    uint32_t aQ[8][4];
    {
        const int row = tid >> 1;
        const int c4  = (tid & 1) * 4;
#pragma unroll
        for (int h2 = 0; h2 < 2; h2++) {
            const float* qp = g_Q + qbase + (size_t)row * HID + h2 * 32;
#pragma unroll
            for (int i = 0; i < 4; i++) {
                int col = c4 + 8 * i;
                float4 v = *(const float4*)(qp + col);
                v.x = f2tf(v.x); v.y = f2tf(v.y); v.z = f2tf(v.z); v.w = f2tf(v.w);
                *(float4*)&Ps[row][col] = v;
            }
            __syncthreads();
#pragma unroll
            for (int ks = 0; ks < 4; ks++) {
                const int f = h2 * 4 + ks;
                const int m0 = 16 * warp + q;
                aQ[f][0] = fbits(Ps[m0    ][ks * 8 + r    ]);
                aQ[f][1] = fbits(Ps[m0 + 8][ks * 8 + r    ]);
                aQ[f][2] = fbits(Ps[m0    ][ks * 8 + r + 4]);
                aQ[f][3] = fbits(Ps[m0 + 8][ks * 8 + r + 4]);
            }
            __syncthreads();
        }
    }

    float o[8][4];
#pragma unroll
    for (int i = 0; i < 8; i++)
#pragma unroll
        for (int j = 0; j < 4; j++) o[i][j] = 0.f;
    float l0 = 0.f, l1 = 0.f;

    const int kr = tid >> 3;          // fill: key row 0..31
    const int c4 = (tid & 7) * 4;     // fill: d col base

    for (int kt = 0; kt < 65; kt++) {
        const int kb = kt * 32;
        // ---- fill K/V tiles (zero-pad past SA) ----
        {
            const bool kval = (kb + kr) < SA;
            const float* kp = g_K + kvbase + (size_t)(kb + kr) * HID;
            const float* vp = g_V + kvbase + (size_t)(kb + kr) * HID;
#pragma unroll
            for (int i = 0; i < 2; i++) {
                int col = c4 + 32 * i;
                float4 kv = kval ? *(const float4*)(kp + col) : make_float4(0,0,0,0);
                kv.x = f2tf(kv.x); kv.y = f2tf(kv.y); kv.z = f2tf(kv.z); kv.w = f2tf(kv.w);
                *(float4*)&Ks[kr][col] = kv;
                float4 vv = kval ? *(const float4*)(vp + col) : make_float4(0,0,0,0);
                vv.x = f2tf(vv.x); vv.y = f2tf(vv.y); vv.z = f2tf(vv.z); vv.w = f2tf(vv.w);
                *(float4*)&Vs[kr][col] = vv;
            }
        }
        __syncthreads();

        // ---- S = Q @ K^T  (16 rows x 32 keys per warp) ----
        float sAcc[4][4];
#pragma unroll
        for (int i = 0; i < 4; i++)
#pragma unroll
            for (int j = 0; j < 4; j++) sAcc[i][j] = 0.f;
#pragma unroll
        for (int ks = 0; ks < 8; ks++) {
            const int k0 = ks * 8;
            uint32_t bf[4][2];
#pragma unroll
            for (int nt = 0; nt < 4; nt++) {
                const int key = nt * 8 + q;
                bf[nt][0] = fbits(Ks[key][k0 + r    ]);
                bf[nt][1] = fbits(Ks[key][k0 + r + 4]);
            }
#pragma unroll
            for (int nt = 0; nt < 4; nt++)
                mma_tf32(sAcc[nt], aQ[ks], bf[nt], sAcc[nt]);
        }

        // ---- P = exp(S/8) with tail masking; write to Ps; row-sum ----
#pragma unroll
        for (int nt = 0; nt < 4; nt++) {
            const int col0 = nt * 8 + 2 * r;
            const int key0 = kb + col0;
            float p0 = (key0     < SA) ? __expf(sAcc[nt][0] * 0.125f) : 0.f;
            float p1 = (key0 + 1 < SA) ? __expf(sAcc[nt][1] * 0.125f) : 0.f;
            float p2 = (key0     < SA) ? __expf(sAcc[nt][2] * 0.125f) : 0.f;
            float p3 = (key0 + 1 < SA) ? __expf(sAcc[nt][3] * 0.125f) : 0.f;
            l0 += p0 + p1;
            l1 += p2 + p3;
            *(float2*)&Ps[16 * warp + q    ][col0] = make_float2(f2tf(p0), f2tf(p1));
            *(float2*)&Ps[16 * warp + q + 8][col0] = make_float2(f2tf(p2), f2tf(p3));
        }
        __syncwarp();

        // ---- O += P @ V  (warp reads only its own Ps rows) ----
#pragma unroll
        for (int ks2 = 0; ks2 < 4; ks2++) {
            const int k0 = ks2 * 8;
            uint32_t aP[4];
            const int m0 = 16 * warp + q;
            aP[0] = fbits(Ps[m0    ][k0 + r    ]);
            aP[1] = fbits(Ps[m0 + 8][k0 + r    ]);
            aP[2] = fbits(Ps[m0    ][k0 + r + 4]);
            aP[3] = fbits(Ps[m0 + 8][k0 + r + 4]);
#pragma unroll
            for (int nt2 = 0; nt2 < 8; nt2++) {
                uint32_t bf2[2];
                bf2[0] = fbits(Vs[k0 + r    ][nt2 * 8 + q]);
                bf2[1] = fbits(Vs[k0 + r + 4][nt2 * 8 + q]);
                mma_tf32(o[nt2], aP, bf2, o[nt2]);
            }
        }
        __syncthreads();
    }

    // ---- finalize: row sums over quad, scale, store ----
    l0 += __shfl_xor_sync(0xFFFFFFFFu, l0, 1);
    l0 += __shfl_xor_sync(0xFFFFFFFFu, l0, 2);
    l1 += __shfl_xor_sync(0xFFFFFFFFu, l1, 1);
    l1 += __shfl_xor_sync(0xFFFFFFFFu, l1, 2);
    const float inv0 = 1.0f / l0;
    const float inv1 = 1.0f / l1;

    const size_t obase = ((size_t)((dir * Bz + b) * SEQ) + qt * 128 + 16 * warp) * HID
                         + h * HD;
#pragma unroll
    for (int nt2 = 0; nt2 < 8; nt2++) {
        const int c = nt2 * 8 + 2 * r;
        *(float2*)(g_att + obase + (size_t)q * HID + c) =
            make_float2(o[nt2][0] * inv0, o[nt2][1] * inv0);
        *(float2*)(g_att + obase + (size_t)(q + 8) * HID + c) =
            make_float2(o[nt2][2] * inv1, o[nt2][3] * inv1);
    }
}

// ---------------------------------------------------------------------------
// Kernel 4: residual + LayerNorm
// ---------------------------------------------------------------------------
__global__ __launch_bounds__(256) void resid_ln(
    const float* __restrict__ cnn, const float* __restrict__ llm,
    const float* __restrict__ gamma, const float* __restrict__ beta,
    float* __restrict__ out)
{
    int row = blockIdx.x;
    int dir = row >> 12;
    int b   = (row >> 11) & 1;
    int s   = row & (SEQ - 1);
    const float* resid = (dir ? llm : cnn) + ((size_t)(b * SEQ + s)) * HID;
    const float* op = g_O + (size_t)row * HID;
    int t = threadIdx.x;

    float4 rv = *(const float4*)(resid + t * 4);
    float4 ov = *(const float4*)(op + t * 4);
    float x0 = rv.x + ov.x, x1 = rv.y + ov.y, x2 = rv.z + ov.z, x3 = rv.w + ov.w;
    float s1 = (x0 + x1) + (x2 + x3);
    float s2 = x0 * x0 + x1 * x1 + x2 * x2 + x3 * x3;
#pragma unroll
    for (int off = 16; off; off >>= 1) {
        s1 += __shfl_xor_sync(0xFFFFFFFFu, s1, off);
        s2 += __shfl_xor_sync(0xFFFFFFFFu, s2, off);
    }
    __shared__ float sm1[8], sm2[8];
    int wp = t >> 5, lane = t & 31;
    if (lane == 0) { sm1[wp] = s1; sm2[wp] = s2; }
    __syncthreads();
    if (t == 0) {
        float a = 0.f, c = 0.f;
#pragma unroll
        for (int i = 0; i < 8; i++) { a += sm1[i]; c += sm2[i]; }
        sm1[0] = a; sm2[0] = c;
    }
    __syncthreads();
    float mean = sm1[0] * (1.0f / HID);
    float var  = sm2[0] * (1.0f / HID) - mean * mean;
    float rstd = rsqrtf(var + 1e-5f);

    float4 g  = *(const float4*)(gamma + t * 4);
    float4 be = *(const float4*)(beta + t * 4);
    float4 y;
    y.x = (x0 - mean) * rstd * g.x + be.x;
    y.y = (x1 - mean) * rstd * g.y + be.y;
    y.z = (x2 - mean) * rstd * g.z + be.z;
    y.w = (x3 - mean) * rstd * g.w + be.w;
    *(float4*)(out + (size_t)row * HID + t * 4) = y;
}

// ---------------------------------------------------------------------------
extern "C" void kernel_launch(void* const* d_in, const int* in_sizes, int n_in,
                              void* d_out, int out_size)
{
    const float* cnn = (const float*)d_in[0];
    const float* llm = (const float*)d_in[1];
    const float* Wq  = (const float*)d_in[2];
    const float* bq  = (const float*)d_in[3];
    const float* Wk  = (const float*)d_in[4];
    const float* bk  = (const float*)d_in[5];
    const float* Wv  = (const float*)d_in[6];
    const float* bv  = (const float*)d_in[7];
    const float* Wo  = (const float*)d_in[8];
    const float* bo  = (const float*)d_in[9];
    const float* ee  = (const float*)d_in[10];
    const float* me  = (const float*)d_in[11];
    const float* pe  = (const float*)d_in[12];
    const float* gamma = (const float*)d_in[13];
    const float* beta  = (const float*)d_in[14];
    float* out = (float*)d_out;

    build_aug<<<2 * Bz * SA, 256>>>(cnn, llm, ee, me, pe);

    {   // QKV projections (6 GEMMs)
        dim3 grid(HID / 128, (Bz * SA + 127) / 128, 6);
        qkv_gemm<<<grid, 256>>>(Wq, bq, Wk, bk, Wv, bv);
    }
    {   // cross-attention, both directions
        dim3 grid(SEQ / 128, NHEADS, 2 * Bz);
        attn_tf32<<<grid, 256>>>();
    }
    {   // output projection (2 GEMMs)
        dim3 grid(HID / 128, (Bz * SEQ) / 128, 2);
        oproj_gemm<<<grid, 256>>>(Wo, bo);
    }
    resid_ln<<<2 * Bz * SEQ, 256>>>(cnn, llm, gamma, beta, out);
}

// round 6
// speedup vs baseline: 5.9994x; 1.5752x over previous
#include <cuda_runtime.h>
#include <cuda_bf16.h>
#include <cstdint>
#include <cstddef>

// ---------------------------------------------------------------------------
// PhysicsInformedAttention — Round 6: bf16 mma.sync m16n8k16 + ldmatrix
// B=2, S=2048, HIDDEN=1024, NH=16, D=64, SA=2051. Physics biases cancel in
// softmax (per-row constants) -> plain cross-attention. fp32 accumulate.
// ---------------------------------------------------------------------------

#define Bz 2
#define SEQ 2048
#define SA 2051
#define HID 1024
#define NHEADS 16
#define HD 64

__device__ float         g_aug [2 * Bz * SA * HID];   // fp32 (QKV GEMM input)
__device__ __nv_bfloat16 g_Qb  [2 * Bz * SA * HID];
__device__ __nv_bfloat16 g_Kb  [2 * Bz * SA * HID];
__device__ __nv_bfloat16 g_Vb  [2 * Bz * SA * HID];
__device__ __nv_bfloat16 g_attb[2 * Bz * SEQ * HID];
__device__ float         g_O   [2 * Bz * SEQ * HID];

// ----------------------------- helpers -------------------------------------
__device__ __forceinline__ uint32_t pk(float a, float b) {
    __nv_bfloat162 h = __floats2bfloat162_rn(a, b);
    return *reinterpret_cast<uint32_t*>(&h);
}

__device__ __forceinline__ void ldsm4(uint32_t& r0, uint32_t& r1, uint32_t& r2,
                                      uint32_t& r3, const void* p) {
    uint32_t a = (uint32_t)__cvta_generic_to_shared(p);
    asm volatile("ldmatrix.sync.aligned.m8n8.x4.shared.b16 {%0,%1,%2,%3}, [%4];"
                 : "=r"(r0), "=r"(r1), "=r"(r2), "=r"(r3) : "r"(a));
}
__device__ __forceinline__ void ldsm4t(uint32_t& r0, uint32_t& r1, uint32_t& r2,
                                       uint32_t& r3, const void* p) {
    uint32_t a = (uint32_t)__cvta_generic_to_shared(p);
    asm volatile("ldmatrix.sync.aligned.m8n8.x4.trans.shared.b16 {%0,%1,%2,%3}, [%4];"
                 : "=r"(r0), "=r"(r1), "=r"(r2), "=r"(r3) : "r"(a));
}
__device__ __forceinline__ void mma_bf16(float* d, const uint32_t* a,
                                         const uint32_t* b) {
    asm volatile(
        "mma.sync.aligned.m16n8k16.row.col.f32.bf16.bf16.f32 "
        "{%0,%1,%2,%3}, {%4,%5,%6,%7}, {%8,%9}, {%0,%1,%2,%3};\n"
        : "+f"(d[0]), "+f"(d[1]), "+f"(d[2]), "+f"(d[3])
        : "r"(a[0]), "r"(a[1]), "r"(a[2]), "r"(a[3]), "r"(b[0]), "r"(b[1]));
}

// ---------------------------------------------------------------------------
// Kernel 1: build augmented tensors
// ---------------------------------------------------------------------------
__global__ __launch_bounds__(256) void build_aug(
    const float* __restrict__ cnn, const float* __restrict__ llm,
    const float* __restrict__ ee, const float* __restrict__ me,
    const float* __restrict__ pe)
{
    int row = blockIdx.x;
    int src = row / (Bz * SA);
    int rem = row - src * (Bz * SA);
    int b   = rem / SA;
    int s   = rem - b * SA;
    const float* p;
    if (s < SEQ) p = (src ? llm : cnn) + ((size_t)(b * SEQ + s)) * HID;
    else         p = (s == SEQ ? ee : (s == SEQ + 1 ? me : pe));
    float* dst = g_aug + (size_t)row * HID;
    int t = threadIdx.x;
    *(float4*)(dst + t * 4) = *(const float4*)(p + t * 4);
}

// ---------------------------------------------------------------------------
// bf16 GEMM body: C[M,1024] = A[M,1024] @ W[1024,1024] + bias
// 128x128 block, kc=32, 8 warps (2x4), warp tile 64x32, m16n8k16 + ldmatrix
// ---------------------------------------------------------------------------
template <bool IN_BF16, bool OUT_BF16>
__device__ __forceinline__ void gemm_body(
    const void* Ain, const float* __restrict__ W,
    const float* __restrict__ bias, void* Cout, int M)
{
    constexpr int N = 1024, K = 1024;
    __shared__ __nv_bfloat16 As[128][40];    // stride 80B = 5x16B (conflict-free)
    __shared__ __nv_bfloat16 Bs[32][136];    // stride 272B = 17x16B

    const int tid  = threadIdx.x;
    const int lane = tid & 31;
    const int warp = tid >> 5;
    const int q = lane >> 2, r = lane & 3;
    const int g = lane >> 3, L = lane & 7;
    const int wm = warp >> 2, wn = warp & 3;
    const int bx = blockIdx.x, by = blockIdx.y;

    // A fill: row = tid/2, 16 cols starting at (tid&1)*16
    const int ar = tid >> 1, ac = (tid & 1) * 16;
    const int agr = by * 128 + ar;
    const bool aval = agr < M;
    // B fill: k = tid/8, 16 cols at (tid&7)*16
    const int br = tid >> 3, bc = (tid & 7) * 16;
    const float* Wb = W + (size_t)br * N + bx * 128 + bc;

    const float* Af = (const float*)Ain + (size_t)agr * K + ac;
    const __nv_bfloat16* Ab = (const __nv_bfloat16*)Ain + (size_t)agr * K + ac;

    float4 apf[4]; uint4 apb[2]; float4 bpf[4];
    if constexpr (IN_BF16) {
        apb[0] = make_uint4(0, 0, 0, 0); apb[1] = make_uint4(0, 0, 0, 0);
        if (aval) { apb[0] = *(const uint4*)(Ab); apb[1] = *(const uint4*)(Ab + 8); }
    } else {
#pragma unroll
        for (int i = 0; i < 4; i++)
            apf[i] = aval ? *(const float4*)(Af + 4 * i) : make_float4(0, 0, 0, 0);
    }
#pragma unroll
    for (int i = 0; i < 4; i++) bpf[i] = *(const float4*)(Wb + 4 * i);

    float acc[16][4];
#pragma unroll
    for (int i = 0; i < 16; i++)
#pragma unroll
        for (int j = 0; j < 4; j++) acc[i][j] = 0.f;

    for (int kb = 0; kb < K; kb += 32) {
        __syncthreads();
        if constexpr (IN_BF16) {
            *(uint4*)&As[ar][ac]     = apb[0];
            *(uint4*)&As[ar][ac + 8] = apb[1];
        } else {
            uint32_t u[8];
#pragma unroll
            for (int i = 0; i < 4; i++) {
                u[2 * i]     = pk(apf[i].x, apf[i].y);
                u[2 * i + 1] = pk(apf[i].z, apf[i].w);
            }
            *(uint4*)&As[ar][ac]     = make_uint4(u[0], u[1], u[2], u[3]);
            *(uint4*)&As[ar][ac + 8] = make_uint4(u[4], u[5], u[6], u[7]);
        }
        {
            uint32_t u[8];
#pragma unroll
            for (int i = 0; i < 4; i++) {
                u[2 * i]     = pk(bpf[i].x, bpf[i].y);
                u[2 * i + 1] = pk(bpf[i].z, bpf[i].w);
            }
            *(uint4*)&Bs[br][bc]     = make_uint4(u[0], u[1], u[2], u[3]);
            *(uint4*)&Bs[br][bc + 8] = make_uint4(u[4], u[5], u[6], u[7]);
        }
        __syncthreads();
        if (kb + 32 < K) {
            if constexpr (IN_BF16) {
                if (aval) {
                    apb[0] = *(const uint4*)(Ab + kb + 32);
                    apb[1] = *(const uint4*)(Ab + kb + 40);
                }
            } else {
#pragma unroll
                for (int i = 0; i < 4; i++)
                    apf[i] = aval ? *(const float4*)(Af + kb + 32 + 4 * i)
                                  : make_float4(0, 0, 0, 0);
            }
#pragma unroll
            for (int i = 0; i < 4; i++)
                bpf[i] = *(const float4*)(Wb + (size_t)(kb + 32) * N + 4 * i);
        }
#pragma unroll
        for (int ks = 0; ks < 2; ks++) {
            const int k0 = ks * 16;
            uint32_t af[4][4];
#pragma unroll
            for (int mt = 0; mt < 4; mt++) {
                const int row = wm * 64 + mt * 16 + (g & 1) * 8 + L;
                const int col = k0 + (g >> 1) * 8;
                ldsm4(af[mt][0], af[mt][1], af[mt][2], af[mt][3], &As[row][col]);
            }
            uint32_t bf[4][2];
#pragma unroll
            for (int np = 0; np < 2; np++) {
                const int row = k0 + (g & 1) * 8 + L;
                const int col = wn * 32 + np * 16 + (g >> 1) * 8;
                uint32_t r0, r1, r2, r3;
                ldsm4t(r0, r1, r2, r3, &Bs[row][col]);
                bf[np * 2][0] = r0; bf[np * 2][1] = r1;
                bf[np * 2 + 1][0] = r2; bf[np * 2 + 1][1] = r3;
            }
#pragma unroll
            for (int mt = 0; mt < 4; mt++)
#pragma unroll
                for (int nt = 0; nt < 4; nt++)
                    mma_bf16(acc[mt * 4 + nt], af[mt], bf[nt]);
        }
    }

    // epilogue
#pragma unroll
    for (int mt = 0; mt < 4; mt++) {
#pragma unroll
        for (int nt = 0; nt < 4; nt++) {
            const int row0 = by * 128 + wm * 64 + mt * 16 + q;
            const int col  = bx * 128 + wn * 32 + nt * 8 + 2 * r;
            const float b0 = bias[col], b1 = bias[col + 1];
            const float* a = acc[mt * 4 + nt];
            if constexpr (OUT_BF16) {
                __nv_bfloat16* C = (__nv_bfloat16*)Cout;
                if (row0 < M)
                    *(uint32_t*)(C + (size_t)row0 * N + col) = pk(a[0] + b0, a[1] + b1);
                if (row0 + 8 < M)
                    *(uint32_t*)(C + (size_t)(row0 + 8) * N + col) = pk(a[2] + b0, a[3] + b1);
            } else {
                float* C = (float*)Cout;
                if (row0 < M)
                    *(float2*)(C + (size_t)row0 * N + col) =
                        make_float2(a[0] + b0, a[1] + b1);
                if (row0 + 8 < M)
                    *(float2*)(C + (size_t)(row0 + 8) * N + col) =
                        make_float2(a[2] + b0, a[3] + b1);
            }
        }
    }
}

__global__ __launch_bounds__(256, 2) void qkv_gemm(
    const float* __restrict__ Wq, const float* __restrict__ bq,
    const float* __restrict__ Wk, const float* __restrict__ bk,
    const float* __restrict__ Wv, const float* __restrict__ bv)
{
    int z = blockIdx.z;
    int src = z / 3, w = z - src * 3;
    const float* A = g_aug + (size_t)src * (Bz * SA * HID);
    const float* Wp; const float* bp; __nv_bfloat16* C;
    if (w == 0)      { Wp = Wq; bp = bq; C = g_Qb; }
    else if (w == 1) { Wp = Wk; bp = bk; C = g_Kb; }
    else             { Wp = Wv; bp = bv; C = g_Vb; }
    C += (size_t)src * (Bz * SA * HID);
    gemm_body<false, true>(A, Wp, bp, C, Bz * SA);
}

__global__ __launch_bounds__(256, 2) void oproj_gemm(
    const float* __restrict__ Wo, const float* __restrict__ bo)
{
    int dir = blockIdx.z;
    gemm_body<true, false>(g_attb + (size_t)dir * (Bz * SEQ * HID), Wo, bo,
                           g_O + (size_t)dir * (Bz * SEQ * HID), Bz * SEQ);
}

// ---------------------------------------------------------------------------
// Flash attention, bf16 mma + ldmatrix. 8 warps; warp owns 16 full q-rows.
// Block: 128 q-rows, Bc=32 keys/iter, D=64.
// ---------------------------------------------------------------------------
__global__ __launch_bounds__(256, 2) void attn_bf16()
{
    __shared__ __nv_bfloat16 Ks[32][72];     // [key][d], stride 144B = 9x16B
    __shared__ __nv_bfloat16 Vs[32][72];
    __shared__ __nv_bfloat16 Ps[128][40];    // [q][key], stride 80B = 5x16B

    const int tid  = threadIdx.x;
    const int lane = tid & 31;
    const int warp = tid >> 5;
    const int q = lane >> 2, r = lane & 3;
    const int g = lane >> 3, L = lane & 7;
    const int m0 = warp * 16;

    const int qt  = blockIdx.x;
    const int h   = blockIdx.y;
    const int dir = blockIdx.z >> 1;
    const int b   = blockIdx.z & 1;

    const __nv_bfloat16* qp =
        g_Qb + ((size_t)((dir * Bz + b) * SA) + qt * 128 + m0) * HID + h * HD;
    const size_t kvbase = ((size_t)(((dir ^ 1) * Bz + b) * SA)) * HID + h * HD;

    // Q fragments straight from gmem (bf16, 4-byte loads at frag positions)
    uint32_t aQ[4][4];
#pragma unroll
    for (int ks = 0; ks < 4; ks++) {
        const int c0 = ks * 16 + 2 * r;
        aQ[ks][0] = *(const uint32_t*)(qp + (size_t)q * HID + c0);
        aQ[ks][1] = *(const uint32_t*)(qp + (size_t)(q + 8) * HID + c0);
        aQ[ks][2] = *(const uint32_t*)(qp + (size_t)q * HID + c0 + 8);
        aQ[ks][3] = *(const uint32_t*)(qp + (size_t)(q + 8) * HID + c0 + 8);
    }

    float o[8][4];
#pragma unroll
    for (int i = 0; i < 8; i++)
#pragma unroll
        for (int j = 0; j < 4; j++) o[i][j] = 0.f;
    float l0 = 0.f, l1 = 0.f;

    const int kr = tid >> 3;
    const int kc = (tid & 7) * 8;

    for (int kt = 0; kt < 65; kt++) {
        const int kb = kt * 32;
        {
            const bool kval = (kb + kr) < SA;
            const __nv_bfloat16* kpp = g_Kb + kvbase + (size_t)(kb + kr) * HID + kc;
            const __nv_bfloat16* vpp = g_Vb + kvbase + (size_t)(kb + kr) * HID + kc;
            uint4 kv = kval ? *(const uint4*)kpp : make_uint4(0, 0, 0, 0);
            uint4 vv = kval ? *(const uint4*)vpp : make_uint4(0, 0, 0, 0);
            *(uint4*)&Ks[kr][kc] = kv;
            *(uint4*)&Vs[kr][kc] = vv;
        }
        __syncthreads();

        // ---- S = Q @ K^T (16 q x 32 keys per warp) ----
        float sAcc[4][4];
#pragma unroll
        for (int i = 0; i < 4; i++)
#pragma unroll
            for (int j = 0; j < 4; j++) sAcc[i][j] = 0.f;
#pragma unroll
        for (int ks = 0; ks < 4; ks++) {
            const int k0 = ks * 16;
            uint32_t bk_[4][2];
#pragma unroll
            for (int half = 0; half < 2; half++) {
                const int row = half * 16 + (g >> 1) * 8 + L;   // key
                const int col = k0 + (g & 1) * 8;               // d
                uint32_t r0, r1, r2, r3;
                ldsm4(r0, r1, r2, r3, &Ks[row][col]);
                bk_[half * 2][0] = r0; bk_[half * 2][1] = r1;
                bk_[half * 2 + 1][0] = r2; bk_[half * 2 + 1][1] = r3;
            }
#pragma unroll
            for (int nt = 0; nt < 4; nt++) mma_bf16(sAcc[nt], aQ[ks], bk_[nt]);
        }

        // ---- P = exp(S/8) with tail masking; write bf16 tile; row-sum ----
#pragma unroll
        for (int nt = 0; nt < 4; nt++) {
            const int col0 = nt * 8 + 2 * r;
            const int key0 = kb + col0;
            float p0 = (key0     < SA) ? __expf(sAcc[nt][0] * 0.125f) : 0.f;
            float p1 = (key0 + 1 < SA) ? __expf(sAcc[nt][1] * 0.125f) : 0.f;
            float p2 = (key0     < SA) ? __expf(sAcc[nt][2] * 0.125f) : 0.f;
            float p3 = (key0 + 1 < SA) ? __expf(sAcc[nt][3] * 0.125f) : 0.f;
            l0 += p0 + p1;
            l1 += p2 + p3;
            *(uint32_t*)&Ps[m0 + q][col0]     = pk(p0, p1);
            *(uint32_t*)&Ps[m0 + q + 8][col0] = pk(p2, p3);
        }
        __syncwarp();

        // ---- O += P @ V ----
#pragma unroll
        for (int ks2 = 0; ks2 < 2; ks2++) {
            const int k0 = ks2 * 16;
            uint32_t aP[4];
            {
                const int row = m0 + (g & 1) * 8 + L;
                const int col = k0 + (g >> 1) * 8;
                ldsm4(aP[0], aP[1], aP[2], aP[3], &Ps[row][col]);
            }
#pragma unroll
            for (int db = 0; db < 4; db++) {
                const int row = k0 + (g & 1) * 8 + L;          // key
                const int col = db * 16 + (g >> 1) * 8;        // d
                uint32_t r0, r1, r2, r3;
                ldsm4t(r0, r1, r2, r3, &Vs[row][col]);
                uint32_t b0[2] = {r0, r1};
                uint32_t b1[2] = {r2, r3};
                mma_bf16(o[db * 2], aP, b0);
                mma_bf16(o[db * 2 + 1], aP, b1);
            }
        }
        __syncthreads();
    }

    // ---- finalize: quad row-sums, scale, bf16 store ----
    l0 += __shfl_xor_sync(0xFFFFFFFFu, l0, 1);
    l0 += __shfl_xor_sync(0xFFFFFFFFu, l0, 2);
    l1 += __shfl_xor_sync(0xFFFFFFFFu, l1, 1);
    l1 += __shfl_xor_sync(0xFFFFFFFFu, l1, 2);
    const float inv0 = 1.0f / l0;
    const float inv1 = 1.0f / l1;

    __nv_bfloat16* op =
        g_attb + ((size_t)((dir * Bz + b) * SEQ) + qt * 128 + m0) * HID + h * HD;
#pragma unroll
    for (int nt2 = 0; nt2 < 8; nt2++) {
        const int c = nt2 * 8 + 2 * r;
        *(uint32_t*)(op + (size_t)q * HID + c) =
            pk(o[nt2][0] * inv0, o[nt2][1] * inv0);
        *(uint32_t*)(op + (size_t)(q + 8) * HID + c) =
            pk(o[nt2][2] * inv1, o[nt2][3] * inv1);
    }
}

// ---------------------------------------------------------------------------
// Kernel 4: residual + LayerNorm (fp32)
// ---------------------------------------------------------------------------
__global__ __launch_bounds__(256) void resid_ln(
    const float* __restrict__ cnn, const float* __restrict__ llm,
    const float* __restrict__ gamma, const float* __restrict__ beta,
    float* __restrict__ out)
{
    int row = blockIdx.x;
    int dir = row >> 12;
    int b   = (row >> 11) & 1;
    int s   = row & (SEQ - 1);
    const float* resid = (dir ? llm : cnn) + ((size_t)(b * SEQ + s)) * HID;
    const float* op = g_O + (size_t)row * HID;
    int t = threadIdx.x;

    float4 rv = *(const float4*)(resid + t * 4);
    float4 ov = *(const float4*)(op + t * 4);
    float x0 = rv.x + ov.x, x1 = rv.y + ov.y, x2 = rv.z + ov.z, x3 = rv.w + ov.w;
    float s1 = (x0 + x1) + (x2 + x3);
    float s2 = x0 * x0 + x1 * x1 + x2 * x2 + x3 * x3;
#pragma unroll
    for (int off = 16; off; off >>= 1) {
        s1 += __shfl_xor_sync(0xFFFFFFFFu, s1, off);
        s2 += __shfl_xor_sync(0xFFFFFFFFu, s2, off);
    }
    __shared__ float sm1[8], sm2[8];
    int wp = t >> 5, lane = t & 31;
    if (lane == 0) { sm1[wp] = s1; sm2[wp] = s2; }
    __syncthreads();
    if (t == 0) {
        float a = 0.f, c = 0.f;
#pragma unroll
        for (int i = 0; i < 8; i++) { a += sm1[i]; c += sm2[i]; }
        sm1[0] = a; sm2[0] = c;
    }
    __syncthreads();
    float mean = sm1[0] * (1.0f / HID);
    float var  = sm2[0] * (1.0f / HID) - mean * mean;
    float rstd = rsqrtf(var + 1e-5f);

    float4 gm = *(const float4*)(gamma + t * 4);
    float4 be = *(const float4*)(beta + t * 4);
    float4 y;
    y.x = (x0 - mean) * rstd * gm.x + be.x;
    y.y = (x1 - mean) * rstd * gm.y + be.y;
    y.z = (x2 - mean) * rstd * gm.z + be.z;
    y.w = (x3 - mean) * rstd * gm.w + be.w;
    *(float4*)(out + (size_t)row * HID + t * 4) = y;
}

// ---------------------------------------------------------------------------
extern "C" void kernel_launch(void* const* d_in, const int* in_sizes, int n_in,
                              void* d_out, int out_size)
{
    const float* cnn = (const float*)d_in[0];
    const float* llm = (const float*)d_in[1];
    const float* Wq  = (const float*)d_in[2];
    const float* bq  = (const float*)d_in[3];
    const float* Wk  = (const float*)d_in[4];
    const float* bk  = (const float*)d_in[5];
    const float* Wv  = (const float*)d_in[6];
    const float* bv  = (const float*)d_in[7];
    const float* Wo  = (const float*)d_in[8];
    const float* bo  = (const float*)d_in[9];
    const float* ee  = (const float*)d_in[10];
    const float* me  = (const float*)d_in[11];
    const float* pe  = (const float*)d_in[12];
    const float* gamma = (const float*)d_in[13];
    const float* beta  = (const float*)d_in[14];
    float* out = (float*)d_out;

    build_aug<<<2 * Bz * SA, 256>>>(cnn, llm, ee, me, pe);

    {   // QKV projections (6 GEMMs)
        dim3 grid(HID / 128, (Bz * SA + 127) / 128, 6);
        qkv_gemm<<<grid, 256>>>(Wq, bq, Wk, bk, Wv, bv);
    }
    {   // cross-attention, both directions
        dim3 grid(SEQ / 128, NHEADS, 2 * Bz);
        attn_bf16<<<grid, 256>>>();
    }
    {   // output projection (2 GEMMs)
        dim3 grid(HID / 128, (Bz * SEQ) / 128, 2);
        oproj_gemm<<<grid, 256>>>(Wo, bo);
    }
    resid_ln<<<2 * Bz * SEQ, 256>>>(cnn, llm, gamma, beta, out);
}

// round 8
// speedup vs baseline: 8.5979x; 1.4331x over previous
#include <cuda_runtime.h>
#include <cuda_bf16.h>
#include <cstdint>
#include <cstddef>

// ---------------------------------------------------------------------------
// PhysicsInformedAttention — Round 8: mma.sync bf16 + cp.async pipelines
// (tcgen05 unavailable: harness emits compute_103 PTX, no 'a' features)
// B=2, S=2048, HIDDEN=1024, NH=16, D=64, SA=2051. Physics biases cancel in
// softmax -> plain cross-attention. fp32 accumulate.
// GEMM: 128x256 block tile, 64x64 warp tile, 2-stage cp.async double buffer.
// ---------------------------------------------------------------------------

#define Bz 2
#define SEQ 2048
#define SA 2051
#define HID 1024
#define NHEADS 16
#define HD 64
#define MAUG (Bz * SA)   /* 4102 */
#define MOUT (Bz * SEQ)  /* 4096 */

__device__ __nv_bfloat16 g_augb[2 * MAUG * HID];   // QKV GEMM input (bf16)
__device__ __nv_bfloat16 g_Wb  [4 * HID * HID];    // W bf16 [k][n] for q,k,v,o
__device__ __nv_bfloat16 g_Qb  [2 * MAUG * HID];
__device__ __nv_bfloat16 g_Kb  [2 * MAUG * HID];
__device__ __nv_bfloat16 g_Vb  [2 * MAUG * HID];
__device__ __nv_bfloat16 g_attb[2 * MOUT * HID];
__device__ float         g_O   [2 * MOUT * HID];

// ----------------------------- helpers -------------------------------------
__device__ __forceinline__ uint32_t pk(float a, float b) {
    __nv_bfloat162 h = __floats2bfloat162_rn(a, b);
    return *reinterpret_cast<uint32_t*>(&h);
}
__device__ __forceinline__ void ldsm4(uint32_t& r0, uint32_t& r1, uint32_t& r2,
                                      uint32_t& r3, const void* p) {
    uint32_t a = (uint32_t)__cvta_generic_to_shared(p);
    asm volatile("ldmatrix.sync.aligned.m8n8.x4.shared.b16 {%0,%1,%2,%3}, [%4];"
                 : "=r"(r0), "=r"(r1), "=r"(r2), "=r"(r3) : "r"(a));
}
__device__ __forceinline__ void ldsm4t(uint32_t& r0, uint32_t& r1, uint32_t& r2,
                                       uint32_t& r3, const void* p) {
    uint32_t a = (uint32_t)__cvta_generic_to_shared(p);
    asm volatile("ldmatrix.sync.aligned.m8n8.x4.trans.shared.b16 {%0,%1,%2,%3}, [%4];"
                 : "=r"(r0), "=r"(r1), "=r"(r2), "=r"(r3) : "r"(a));
}
__device__ __forceinline__ void mma_bf16(float* d, const uint32_t* a,
                                         const uint32_t* b) {
    asm volatile(
        "mma.sync.aligned.m16n8k16.row.col.f32.bf16.bf16.f32 "
        "{%0,%1,%2,%3}, {%4,%5,%6,%7}, {%8,%9}, {%0,%1,%2,%3};\n"
        : "+f"(d[0]), "+f"(d[1]), "+f"(d[2]), "+f"(d[3])
        : "r"(a[0]), "r"(a[1]), "r"(a[2]), "r"(a[3]), "r"(b[0]), "r"(b[1]));
}
// 16B cp.async with zero-fill predication (src_size = 0 -> all zeros)
__device__ __forceinline__ void cpa16(uint32_t dst, const void* src, bool ok) {
    int sz = ok ? 16 : 0;
    asm volatile("cp.async.cg.shared.global [%0], [%1], 16, %2;"
                 :: "r"(dst), "l"(src), "r"(sz) : "memory");
}
#define CPA_COMMIT() asm volatile("cp.async.commit_group;" ::: "memory")
#define CPA_WAIT1()  asm volatile("cp.async.wait_group 1;" ::: "memory")

// ---------------------------------------------------------------------------
// Kernel 0: fp32 -> bf16 convert of W (4 matrices, natural [k][n] layout)
// ---------------------------------------------------------------------------
__global__ __launch_bounds__(256) void conv_w(
    const float* __restrict__ Wq, const float* __restrict__ Wk,
    const float* __restrict__ Wv, const float* __restrict__ Wo)
{
    int i4 = blockIdx.x * 256 + threadIdx.x;       // float4 index, 0..1048575
    int w  = i4 >> 18;                             // / 262144
    int e  = i4 & 262143;
    const float* W = (w == 0) ? Wq : (w == 1) ? Wk : (w == 2) ? Wv : Wo;
    float4 v = ((const float4*)W)[e];
    *(uint2*)(g_Wb + (size_t)w * HID * HID + (size_t)e * 4) =
        make_uint2(pk(v.x, v.y), pk(v.z, v.w));
}

// ---------------------------------------------------------------------------
// Kernel 1: build augmented tensors -> bf16
// ---------------------------------------------------------------------------
__global__ __launch_bounds__(256) void build_aug(
    const float* __restrict__ cnn, const float* __restrict__ llm,
    const float* __restrict__ ee, const float* __restrict__ me,
    const float* __restrict__ pe)
{
    int row = blockIdx.x;
    int src = row / MAUG;
    int rem = row - src * MAUG;
    int b   = rem / SA;
    int s   = rem - b * SA;
    const float* p;
    if (s < SEQ) p = (src ? llm : cnn) + ((size_t)(b * SEQ + s)) * HID;
    else         p = (s == SEQ ? ee : (s == SEQ + 1 ? me : pe));
    __nv_bfloat16* dst = g_augb + (size_t)row * HID;
    int t = threadIdx.x;
    float4 v = *(const float4*)(p + t * 4);
    *(uint2*)(dst + t * 4) = make_uint2(pk(v.x, v.y), pk(v.z, v.w));
}

// ---------------------------------------------------------------------------
// bf16 GEMM: C[M,1024] = A[M,1024] @ W[1024,1024] + bias
// 128x256 block tile, kc=32, 8 warps 2x4, warp tile 64x64,
// 2-stage cp.async double buffer. smem (dynamic): A 2x128x40, B 2x32x264.
// ---------------------------------------------------------------------------
#define AS_STRIDE 40
#define BS_STRIDE 264
#define AS_STG (128 * AS_STRIDE)
#define BS_STG (32 * BS_STRIDE)
#define GEMM_SMEM ((2 * AS_STG + 2 * BS_STG) * 2)

template <bool OUT_BF16>
__device__ __forceinline__ void gemm_body(
    const __nv_bfloat16* __restrict__ A, const __nv_bfloat16* __restrict__ Wb,
    const float* __restrict__ bias, void* Cout, int M)
{
    extern __shared__ char smraw[];
    __nv_bfloat16* Asm = (__nv_bfloat16*)smraw;          // [2][128][40]
    __nv_bfloat16* Bsm = Asm + 2 * AS_STG;               // [2][32][264]
    const uint32_t As_u = (uint32_t)__cvta_generic_to_shared(Asm);
    const uint32_t Bs_u = (uint32_t)__cvta_generic_to_shared(Bsm);

    const int tid  = threadIdx.x;
    const int lane = tid & 31;
    const int warp = tid >> 5;
    const int q = lane >> 2, r = lane & 3;
    const int g = lane >> 3, L = lane & 7;
    const int wm = warp >> 2, wn = warp & 3;
    const int bx = blockIdx.x, by = blockIdx.y;

    // fill-index precompute
    const int arow = tid >> 2, aseg = tid & 3;           // A: j = tid + 256i
    const int brow = tid >> 5, bseg = tid & 31;          // B: j = tid + 256i

    float acc[4][8][4];
#pragma unroll
    for (int i = 0; i < 4; i++)
#pragma unroll
        for (int j = 0; j < 8; j++)
#pragma unroll
            for (int k = 0; k < 4; k++) acc[i][j][k] = 0.f;

    auto fill = [&](int c, int s) {
#pragma unroll
        for (int i = 0; i < 2; i++) {
            const int row = arow + i * 64;
            const int gr  = by * 128 + row;
            const bool ok = gr < M;
            const __nv_bfloat16* src =
                A + (size_t)(ok ? gr : (M - 1)) * HID + c * 32 + aseg * 8;
            cpa16(As_u + (uint32_t)(s * AS_STG + row * AS_STRIDE + aseg * 8) * 2,
                  src, ok);
        }
#pragma unroll
        for (int i = 0; i < 4; i++) {
            const int row = brow + i * 8;
            const __nv_bfloat16* src =
                Wb + (size_t)(c * 32 + row) * HID + bx * 256 + bseg * 8;
            cpa16(Bs_u + (uint32_t)(s * BS_STG + row * BS_STRIDE + bseg * 8) * 2,
                  src, true);
        }
    };

    fill(0, 0);
    CPA_COMMIT();

    for (int it = 0; it < 32; it++) {
        __syncthreads();                        // prior compute done on next stage
        if (it + 1 < 32) fill(it + 1, (it + 1) & 1);
        CPA_COMMIT();
        CPA_WAIT1();                            // chunk `it` complete
        __syncthreads();                        // visible to all warps

        const __nv_bfloat16* Aps = Asm + (it & 1) * AS_STG;
        const __nv_bfloat16* Bps = Bsm + (it & 1) * BS_STG;
#pragma unroll
        for (int ks = 0; ks < 2; ks++) {
            const int k0 = ks * 16;
            uint32_t af[4][4];
#pragma unroll
            for (int mt = 0; mt < 4; mt++) {
                const int row = wm * 64 + mt * 16 + (g & 1) * 8 + L;
                ldsm4(af[mt][0], af[mt][1], af[mt][2], af[mt][3],
                      Aps + row * AS_STRIDE + k0 + (g >> 1) * 8);
            }
            uint32_t bf[8][2];
#pragma unroll
            for (int np = 0; np < 4; np++) {
                const int row = k0 + (g & 1) * 8 + L;
                const int col = wn * 64 + np * 16 + (g >> 1) * 8;
                uint32_t r0, r1, r2, r3;
                ldsm4t(r0, r1, r2, r3, Bps + row * BS_STRIDE + col);
                bf[np * 2][0] = r0; bf[np * 2][1] = r1;
                bf[np * 2 + 1][0] = r2; bf[np * 2 + 1][1] = r3;
            }
#pragma unroll
            for (int mt = 0; mt < 4; mt++)
#pragma unroll
                for (int nt = 0; nt < 8; nt++)
                    mma_bf16(acc[mt][nt], af[mt], bf[nt]);
        }
    }

    // epilogue
#pragma unroll
    for (int mt = 0; mt < 4; mt++) {
#pragma unroll
        for (int nt = 0; nt < 8; nt++) {
            const int row0 = by * 128 + wm * 64 + mt * 16 + q;
            const int col  = bx * 256 + wn * 64 + nt * 8 + 2 * r;
            const float b0 = bias[col], b1 = bias[col + 1];
            const float* a = acc[mt][nt];
            if constexpr (OUT_BF16) {
                __nv_bfloat16* C = (__nv_bfloat16*)Cout;
                if (row0 < M)
                    *(uint32_t*)(C + (size_t)row0 * HID + col) = pk(a[0] + b0, a[1] + b1);
                if (row0 + 8 < M)
                    *(uint32_t*)(C + (size_t)(row0 + 8) * HID + col) = pk(a[2] + b0, a[3] + b1);
            } else {
                float* C = (float*)Cout;
                if (row0 < M)
                    *(float2*)(C + (size_t)row0 * HID + col) =
                        make_float2(a[0] + b0, a[1] + b1);
                if (row0 + 8 < M)
                    *(float2*)(C + (size_t)(row0 + 8) * HID + col) =
                        make_float2(a[2] + b0, a[3] + b1);
            }
        }
    }
}

__global__ __launch_bounds__(256) void qkv_gemm(
    const float* __restrict__ bq, const float* __restrict__ bk,
    const float* __restrict__ bv)
{
    int z = blockIdx.z;
    int src = z / 3, w = z - src * 3;
    const __nv_bfloat16* A = g_augb + (size_t)src * MAUG * HID;
    const __nv_bfloat16* Wb = g_Wb + (size_t)w * HID * HID;
    const float* bp = (w == 0) ? bq : (w == 1) ? bk : bv;
    __nv_bfloat16* C = ((w == 0) ? g_Qb : (w == 1) ? g_Kb : g_Vb)
                       + (size_t)src * MAUG * HID;
    gemm_body<true>(A, Wb, bp, C, MAUG);
}

__global__ __launch_bounds__(256) void oproj_gemm(const float* __restrict__ bo)
{
    int dir = blockIdx.z;
    gemm_body<false>(g_attb + (size_t)dir * MOUT * HID,
                     g_Wb + (size_t)3 * HID * HID, bo,
                     g_O + (size_t)dir * MOUT * HID, MOUT);
}

// ---------------------------------------------------------------------------
// Flash attention, bf16 mma + ldmatrix + cp.async double-buffered K/V.
// 8 warps; warp owns 16 full q-rows. Block: 128 q, Bc=32 keys/iter, D=64.
// ---------------------------------------------------------------------------
__global__ __launch_bounds__(256, 2) void attn_bf16()
{
    __shared__ alignas(16) __nv_bfloat16 Kst[2][32][72];
    __shared__ alignas(16) __nv_bfloat16 Vst[2][32][72];
    __shared__ alignas(16) __nv_bfloat16 Ps[128][40];

    const int tid  = threadIdx.x;
    const int lane = tid & 31;
    const int warp = tid >> 5;
    const int q = lane >> 2, r = lane & 3;
    const int g = lane >> 3, L = lane & 7;
    const int m0 = warp * 16;

    const int qt  = blockIdx.x;
    const int h   = blockIdx.y;
    const int dir = blockIdx.z >> 1;
    const int b   = blockIdx.z & 1;

    const __nv_bfloat16* qp =
        g_Qb + ((size_t)((dir * Bz + b) * SA) + qt * 128 + m0) * HID + h * HD;
    const size_t kvbase = ((size_t)(((dir ^ 1) * Bz + b) * SA)) * HID + h * HD;

    const uint32_t K_u = (uint32_t)__cvta_generic_to_shared(&Kst[0][0][0]);
    const uint32_t V_u = (uint32_t)__cvta_generic_to_shared(&Vst[0][0][0]);
    const int frow = tid >> 3, fseg = tid & 7;

    auto fill = [&](int t, int s) {
        const int key = t * 32 + frow;
        const bool ok = key < SA;
        const size_t off = kvbase + (size_t)(ok ? key : 0) * HID + fseg * 8;
        const uint32_t d = (uint32_t)(s * 32 * 72 + frow * 72 + fseg * 8) * 2;
        cpa16(K_u + d, g_Kb + off, ok);
        cpa16(V_u + d, g_Vb + off, ok);
    };

    // Q fragments straight from gmem
    uint32_t aQ[4][4];
#pragma unroll
    for (int ks = 0; ks < 4; ks++) {
        const int c0 = ks * 16 + 2 * r;
        aQ[ks][0] = *(const uint32_t*)(qp + (size_t)q * HID + c0);
        aQ[ks][1] = *(const uint32_t*)(qp + (size_t)(q + 8) * HID + c0);
        aQ[ks][2] = *(const uint32_t*)(qp + (size_t)q * HID + c0 + 8);
        aQ[ks][3] = *(const uint32_t*)(qp + (size_t)(q + 8) * HID + c0 + 8);
    }

    float o[8][4];
#pragma unroll
    for (int i = 0; i < 8; i++)
#pragma unroll
        for (int j = 0; j < 4; j++) o[i][j] = 0.f;
    float l0 = 0.f, l1 = 0.f;

    fill(0, 0);
    CPA_COMMIT();

    for (int kt = 0; kt < 65; kt++) {
        const int kb = kt * 32;
        const int s  = kt & 1;
        __syncthreads();
        if (kt + 1 < 65) fill(kt + 1, (kt + 1) & 1);
        CPA_COMMIT();
        CPA_WAIT1();
        __syncthreads();

        // ---- S = Q @ K^T (16 q x 32 keys per warp) ----
        float sAcc[4][4];
#pragma unroll
        for (int i = 0; i < 4; i++)
#pragma unroll
            for (int j = 0; j < 4; j++) sAcc[i][j] = 0.f;
#pragma unroll
        for (int ks = 0; ks < 4; ks++) {
            const int k0 = ks * 16;
            uint32_t bk_[4][2];
#pragma unroll
            for (int half = 0; half < 2; half++) {
                const int row = half * 16 + (g >> 1) * 8 + L;
                const int col = k0 + (g & 1) * 8;
                uint32_t r0, r1, r2, r3;
                ldsm4(r0, r1, r2, r3, &Kst[s][row][col]);
                bk_[half * 2][0] = r0; bk_[half * 2][1] = r1;
                bk_[half * 2 + 1][0] = r2; bk_[half * 2 + 1][1] = r3;
            }
#pragma unroll
            for (int nt = 0; nt < 4; nt++) mma_bf16(sAcc[nt], aQ[ks], bk_[nt]);
        }

        // ---- P = exp(S/8), masked; bf16 tile; row-sum ----
#pragma unroll
        for (int nt = 0; nt < 4; nt++) {
            const int col0 = nt * 8 + 2 * r;
            const int key0 = kb + col0;
            float p0 = (key0     < SA) ? __expf(sAcc[nt][0] * 0.125f) : 0.f;
            float p1 = (key0 + 1 < SA) ? __expf(sAcc[nt][1] * 0.125f) : 0.f;
            float p2 = (key0     < SA) ? __expf(sAcc[nt][2] * 0.125f) : 0.f;
            float p3 = (key0 + 1 < SA) ? __expf(sAcc[nt][3] * 0.125f) : 0.f;
            l0 += p0 + p1;
            l1 += p2 + p3;
            *(uint32_t*)&Ps[m0 + q][col0]     = pk(p0, p1);
            *(uint32_t*)&Ps[m0 + q + 8][col0] = pk(p2, p3);
        }
        __syncwarp();

        // ---- O += P @ V ----
#pragma unroll
        for (int ks2 = 0; ks2 < 2; ks2++) {
            const int k0 = ks2 * 16;
            uint32_t aP[4];
            {
                const int row = m0 + (g & 1) * 8 + L;
                const int col = k0 + (g >> 1) * 8;
                ldsm4(aP[0], aP[1], aP[2], aP[3], &Ps[row][col]);
            }
#pragma unroll
            for (int db = 0; db < 4; db++) {
                const int row = k0 + (g & 1) * 8 + L;
                const int col = db * 16 + (g >> 1) * 8;
                uint32_t r0, r1, r2, r3;
                ldsm4t(r0, r1, r2, r3, &Vst[s][row][col]);
                uint32_t b0[2] = {r0, r1};
                uint32_t b1[2] = {r2, r3};
                mma_bf16(o[db * 2], aP, b0);
                mma_bf16(o[db * 2 + 1], aP, b1);
            }
        }
    }

    l0 += __shfl_xor_sync(0xFFFFFFFFu, l0, 1);
    l0 += __shfl_xor_sync(0xFFFFFFFFu, l0, 2);
    l1 += __shfl_xor_sync(0xFFFFFFFFu, l1, 1);
    l1 += __shfl_xor_sync(0xFFFFFFFFu, l1, 2);
    const float inv0 = 1.0f / l0;
    const float inv1 = 1.0f / l1;

    __nv_bfloat16* op =
        g_attb + ((size_t)((dir * Bz + b) * SEQ) + qt * 128 + m0) * HID + h * HD;
#pragma unroll
    for (int nt2 = 0; nt2 < 8; nt2++) {
        const int c = nt2 * 8 + 2 * r;
        *(uint32_t*)(op + (size_t)q * HID + c) =
            pk(o[nt2][0] * inv0, o[nt2][1] * inv0);
        *(uint32_t*)(op + (size_t)(q + 8) * HID + c) =
            pk(o[nt2][2] * inv1, o[nt2][3] * inv1);
    }
}

// ---------------------------------------------------------------------------
// Kernel 4: residual + LayerNorm (fp32)
// ---------------------------------------------------------------------------
__global__ __launch_bounds__(256) void resid_ln(
    const float* __restrict__ cnn, const float* __restrict__ llm,
    const float* __restrict__ gamma, const float* __restrict__ beta,
    float* __restrict__ out)
{
    int row = blockIdx.x;
    int dir = row >> 12;
    int b   = (row >> 11) & 1;
    int s   = row & (SEQ - 1);
    const float* resid = (dir ? llm : cnn) + ((size_t)(b * SEQ + s)) * HID;
    const float* op = g_O + (size_t)row * HID;
    int t = threadIdx.x;

    float4 rv = *(const float4*)(resid + t * 4);
    float4 ov = *(const float4*)(op + t * 4);
    float x0 = rv.x + ov.x, x1 = rv.y + ov.y, x2 = rv.z + ov.z, x3 = rv.w + ov.w;
    float s1 = (x0 + x1) + (x2 + x3);
    float s2 = x0 * x0 + x1 * x1 + x2 * x2 + x3 * x3;
#pragma unroll
    for (int off = 16; off; off >>= 1) {
        s1 += __shfl_xor_sync(0xFFFFFFFFu, s1, off);
        s2 += __shfl_xor_sync(0xFFFFFFFFu, s2, off);
    }
    __shared__ float sm1[8], sm2[8];
    int wp = t >> 5, lane = t & 31;
    if (lane == 0) { sm1[wp] = s1; sm2[wp] = s2; }
    __syncthreads();
    if (t == 0) {
        float a = 0.f, c = 0.f;
#pragma unroll
        for (int i = 0; i < 8; i++) { a += sm1[i]; c += sm2[i]; }
        sm1[0] = a; sm2[0] = c;
    }
    __syncthreads();
    float mean = sm1[0] * (1.0f / HID);
    float var  = sm2[0] * (1.0f / HID) - mean * mean;
    float rstd = rsqrtf(var + 1e-5f);

    float4 gm = *(const float4*)(gamma + t * 4);
    float4 be = *(const float4*)(beta + t * 4);
    float4 y;
    y.x = (x0 - mean) * rstd * gm.x + be.x;
    y.y = (x1 - mean) * rstd * gm.y + be.y;
    y.z = (x2 - mean) * rstd * gm.z + be.z;
    y.w = (x3 - mean) * rstd * gm.w + be.w;
    *(float4*)(out + (size_t)row * HID + t * 4) = y;
}

// ---------------------------------------------------------------------------
extern "C" void kernel_launch(void* const* d_in, const int* in_sizes, int n_in,
                              void* d_out, int out_size)
{
    const float* cnn = (const float*)d_in[0];
    const float* llm = (const float*)d_in[1];
    const float* Wq  = (const float*)d_in[2];
    const float* bq  = (const float*)d_in[3];
    const float* Wk  = (const float*)d_in[4];
    const float* bk  = (const float*)d_in[5];
    const float* Wv  = (const float*)d_in[6];
    const float* bv  = (const float*)d_in[7];
    const float* Wo  = (const float*)d_in[8];
    const float* bo  = (const float*)d_in[9];
    const float* ee  = (const float*)d_in[10];
    const float* me  = (const float*)d_in[11];
    const float* pe  = (const float*)d_in[12];
    const float* gamma = (const float*)d_in[13];
    const float* beta  = (const float*)d_in[14];
    float* out = (float*)d_out;

    cudaFuncSetAttribute(qkv_gemm,
                         cudaFuncAttributeMaxDynamicSharedMemorySize, GEMM_SMEM);
    cudaFuncSetAttribute(oproj_gemm,
                         cudaFuncAttributeMaxDynamicSharedMemorySize, GEMM_SMEM);

    conv_w<<<4096, 256>>>(Wq, Wk, Wv, Wo);
    build_aug<<<2 * MAUG, 256>>>(cnn, llm, ee, me, pe);

    {   // QKV projections (6 GEMMs)
        dim3 grid(HID / 256, (MAUG + 127) / 128, 6);
        qkv_gemm<<<grid, 256, GEMM_SMEM>>>(bq, bk, bv);
    }
    {   // cross-attention, both directions
        dim3 grid(SEQ / 128, NHEADS, 2 * Bz);
        attn_bf16<<<grid, 256>>>();
    }
    {   // output projection (2 GEMMs)
        dim3 grid(HID / 256, MOUT / 128, 2);
        oproj_gemm<<<grid, 256, GEMM_SMEM>>>(bo);
    }
    resid_ln<<<2 * Bz * SEQ, 256>>>(cnn, llm, gamma, beta, out);
}

// round 9
// speedup vs baseline: 9.3936x; 1.0925x over previous
#include <cuda_runtime.h>
#include <cuda_bf16.h>
#include <cstdint>
#include <cstddef>

// ---------------------------------------------------------------------------
// PhysicsInformedAttention — Round 9: register-resident P (FA-2 trick),
// 3-stage cp.async pipelines, single-barrier loops.
// B=2, S=2048, HIDDEN=1024, NH=16, D=64, SA=2051. Physics biases cancel.
// ---------------------------------------------------------------------------

#define Bz 2
#define SEQ 2048
#define SA 2051
#define HID 1024
#define NHEADS 16
#define HD 64
#define MAUG (Bz * SA)   /* 4102 */
#define MOUT (Bz * SEQ)  /* 4096 */

__device__ __nv_bfloat16 g_augb[2 * MAUG * HID];
__device__ __nv_bfloat16 g_Wb  [4 * HID * HID];    // W bf16 [k][n] for q,k,v,o
__device__ __nv_bfloat16 g_Qb  [2 * MAUG * HID];
__device__ __nv_bfloat16 g_Kb  [2 * MAUG * HID];
__device__ __nv_bfloat16 g_Vb  [2 * MAUG * HID];
__device__ __nv_bfloat16 g_attb[2 * MOUT * HID];
__device__ float         g_O   [2 * MOUT * HID];

// ----------------------------- helpers -------------------------------------
__device__ __forceinline__ uint32_t pk(float a, float b) {
    __nv_bfloat162 h = __floats2bfloat162_rn(a, b);
    return *reinterpret_cast<uint32_t*>(&h);
}
__device__ __forceinline__ void ldsm4(uint32_t& r0, uint32_t& r1, uint32_t& r2,
                                      uint32_t& r3, const void* p) {
    uint32_t a = (uint32_t)__cvta_generic_to_shared(p);
    asm volatile("ldmatrix.sync.aligned.m8n8.x4.shared.b16 {%0,%1,%2,%3}, [%4];"
                 : "=r"(r0), "=r"(r1), "=r"(r2), "=r"(r3) : "r"(a));
}
__device__ __forceinline__ void ldsm4t(uint32_t& r0, uint32_t& r1, uint32_t& r2,
                                       uint32_t& r3, const void* p) {
    uint32_t a = (uint32_t)__cvta_generic_to_shared(p);
    asm volatile("ldmatrix.sync.aligned.m8n8.x4.trans.shared.b16 {%0,%1,%2,%3}, [%4];"
                 : "=r"(r0), "=r"(r1), "=r"(r2), "=r"(r3) : "r"(a));
}
__device__ __forceinline__ void mma_bf16(float* d, const uint32_t* a,
                                         const uint32_t* b) {
    asm volatile(
        "mma.sync.aligned.m16n8k16.row.col.f32.bf16.bf16.f32 "
        "{%0,%1,%2,%3}, {%4,%5,%6,%7}, {%8,%9}, {%0,%1,%2,%3};\n"
        : "+f"(d[0]), "+f"(d[1]), "+f"(d[2]), "+f"(d[3])
        : "r"(a[0]), "r"(a[1]), "r"(a[2]), "r"(a[3]), "r"(b[0]), "r"(b[1]));
}
__device__ __forceinline__ void cpa16(uint32_t dst, const void* src, bool ok) {
    int sz = ok ? 16 : 0;
    asm volatile("cp.async.cg.shared.global [%0], [%1], 16, %2;"
                 :: "r"(dst), "l"(src), "r"(sz) : "memory");
}
#define CPA_COMMIT() asm volatile("cp.async.commit_group;" ::: "memory")
#define CPA_WAIT1()  asm volatile("cp.async.wait_group 1;" ::: "memory")

// ---------------------------------------------------------------------------
// Kernel 0: fp32 -> bf16 convert of W (4 matrices)
// ---------------------------------------------------------------------------
__global__ __launch_bounds__(256) void conv_w(
    const float* __restrict__ Wq, const float* __restrict__ Wk,
    const float* __restrict__ Wv, const float* __restrict__ Wo)
{
    int i4 = blockIdx.x * 256 + threadIdx.x;
    int w  = i4 >> 18;
    int e  = i4 & 262143;
    const float* W = (w == 0) ? Wq : (w == 1) ? Wk : (w == 2) ? Wv : Wo;
    float4 v = ((const float4*)W)[e];
    *(uint2*)(g_Wb + (size_t)w * HID * HID + (size_t)e * 4) =
        make_uint2(pk(v.x, v.y), pk(v.z, v.w));
}

// ---------------------------------------------------------------------------
// Kernel 1: build augmented tensors -> bf16
// ---------------------------------------------------------------------------
__global__ __launch_bounds__(256) void build_aug(
    const float* __restrict__ cnn, const float* __restrict__ llm,
    const float* __restrict__ ee, const float* __restrict__ me,
    const float* __restrict__ pe)
{
    int row = blockIdx.x;
    int src = row / MAUG;
    int rem = row - src * MAUG;
    int b   = rem / SA;
    int s   = rem - b * SA;
    const float* p;
    if (s < SEQ) p = (src ? llm : cnn) + ((size_t)(b * SEQ + s)) * HID;
    else         p = (s == SEQ ? ee : (s == SEQ + 1 ? me : pe));
    __nv_bfloat16* dst = g_augb + (size_t)row * HID;
    int t = threadIdx.x;
    float4 v = *(const float4*)(p + t * 4);
    *(uint2*)(dst + t * 4) = make_uint2(pk(v.x, v.y), pk(v.z, v.w));
}

// ---------------------------------------------------------------------------
// bf16 GEMM: C[M,1024] = A[M,1024] @ W[1024,1024] + bias
// 128x256 block, kc=32, 8 warps 2x4, warp tile 64x64, 3-stage cp.async.
// ---------------------------------------------------------------------------
#define AS_STRIDE 40
#define BS_STRIDE 264
#define AS_STG (128 * AS_STRIDE)
#define BS_STG (32 * BS_STRIDE)
#define GEMM_SMEM ((3 * AS_STG + 3 * BS_STG) * 2)

template <bool OUT_BF16>
__device__ __forceinline__ void gemm_body(
    const __nv_bfloat16* __restrict__ A, const __nv_bfloat16* __restrict__ Wb,
    const float* __restrict__ bias, void* Cout, int M)
{
    extern __shared__ char smraw[];
    __nv_bfloat16* Asm = (__nv_bfloat16*)smraw;          // [3][128][40]
    __nv_bfloat16* Bsm = Asm + 3 * AS_STG;               // [3][32][264]
    const uint32_t As_u = (uint32_t)__cvta_generic_to_shared(Asm);
    const uint32_t Bs_u = (uint32_t)__cvta_generic_to_shared(Bsm);

    const int tid  = threadIdx.x;
    const int lane = tid & 31;
    const int warp = tid >> 5;
    const int q = lane >> 2, r = lane & 3;
    const int g = lane >> 3, L = lane & 7;
    const int wm = warp >> 2, wn = warp & 3;
    const int bx = blockIdx.x, by = blockIdx.y;

    const int arow = tid >> 2, aseg = tid & 3;
    const int brow = tid >> 5, bseg = tid & 31;

    float acc[4][8][4];
#pragma unroll
    for (int i = 0; i < 4; i++)
#pragma unroll
        for (int j = 0; j < 8; j++)
#pragma unroll
            for (int k = 0; k < 4; k++) acc[i][j][k] = 0.f;

    auto fill = [&](int c, int s) {
#pragma unroll
        for (int i = 0; i < 2; i++) {
            const int row = arow + i * 64;
            const int gr  = by * 128 + row;
            const bool ok = gr < M;
            const __nv_bfloat16* src =
                A + (size_t)(ok ? gr : (M - 1)) * HID + c * 32 + aseg * 8;
            cpa16(As_u + (uint32_t)(s * AS_STG + row * AS_STRIDE + aseg * 8) * 2,
                  src, ok);
        }
#pragma unroll
        for (int i = 0; i < 4; i++) {
            const int row = brow + i * 8;
            const __nv_bfloat16* src =
                Wb + (size_t)(c * 32 + row) * HID + bx * 256 + bseg * 8;
            cpa16(Bs_u + (uint32_t)(s * BS_STG + row * BS_STRIDE + bseg * 8) * 2,
                  src, true);
        }
    };

    fill(0, 0); CPA_COMMIT();
    fill(1, 1); CPA_COMMIT();

    int st = 0;
    for (int it = 0; it < 32; it++) {
        CPA_WAIT1();
        __syncthreads();
        if (it + 2 < 32) {
            int s2 = st + 2; if (s2 >= 3) s2 -= 3;
            fill(it + 2, s2);
        }
        CPA_COMMIT();

        const __nv_bfloat16* Aps = Asm + st * AS_STG;
        const __nv_bfloat16* Bps = Bsm + st * BS_STG;
#pragma unroll
        for (int ks = 0; ks < 2; ks++) {
            const int k0 = ks * 16;
            uint32_t af[4][4];
#pragma unroll
            for (int mt = 0; mt < 4; mt++) {
                const int row = wm * 64 + mt * 16 + (g & 1) * 8 + L;
                ldsm4(af[mt][0], af[mt][1], af[mt][2], af[mt][3],
                      Aps + row * AS_STRIDE + k0 + (g >> 1) * 8);
            }
            uint32_t bf[8][2];
#pragma unroll
            for (int np = 0; np < 4; np++) {
                const int row = k0 + (g & 1) * 8 + L;
                const int col = wn * 64 + np * 16 + (g >> 1) * 8;
                uint32_t r0, r1, r2, r3;
                ldsm4t(r0, r1, r2, r3, Bps + row * BS_STRIDE + col);
                bf[np * 2][0] = r0; bf[np * 2][1] = r1;
                bf[np * 2 + 1][0] = r2; bf[np * 2 + 1][1] = r3;
            }
#pragma unroll
            for (int mt = 0; mt < 4; mt++)
#pragma unroll
                for (int nt = 0; nt < 8; nt++)
                    mma_bf16(acc[mt][nt], af[mt], bf[nt]);
        }
        if (++st >= 3) st = 0;
    }

    // epilogue
#pragma unroll
    for (int mt = 0; mt < 4; mt++) {
#pragma unroll
        for (int nt = 0; nt < 8; nt++) {
            const int row0 = by * 128 + wm * 64 + mt * 16 + q;
            const int col  = bx * 256 + wn * 64 + nt * 8 + 2 * r;
            const float b0 = bias[col], b1 = bias[col + 1];
            const float* a = acc[mt][nt];
            if constexpr (OUT_BF16) {
                __nv_bfloat16* C = (__nv_bfloat16*)Cout;
                if (row0 < M)
                    *(uint32_t*)(C + (size_t)row0 * HID + col) = pk(a[0] + b0, a[1] + b1);
                if (row0 + 8 < M)
                    *(uint32_t*)(C + (size_t)(row0 + 8) * HID + col) = pk(a[2] + b0, a[3] + b1);
            } else {
                float* C = (float*)Cout;
                if (row0 < M)
                    *(float2*)(C + (size_t)row0 * HID + col) =
                        make_float2(a[0] + b0, a[1] + b1);
                if (row0 + 8 < M)
                    *(float2*)(C + (size_t)(row0 + 8) * HID + col) =
                        make_float2(a[2] + b0, a[3] + b1);
            }
        }
    }
}

__global__ __launch_bounds__(256) void qkv_gemm(
    const float* __restrict__ bq, const float* __restrict__ bk,
    const float* __restrict__ bv)
{
    int z = blockIdx.z;
    int src = z / 3, w = z - src * 3;
    const __nv_bfloat16* A = g_augb + (size_t)src * MAUG * HID;
    const __nv_bfloat16* Wb = g_Wb + (size_t)w * HID * HID;
    const float* bp = (w == 0) ? bq : (w == 1) ? bk : bv;
    __nv_bfloat16* C = ((w == 0) ? g_Qb : (w == 1) ? g_Kb : g_Vb)
                       + (size_t)src * MAUG * HID;
    gemm_body<true>(A, Wb, bp, C, MAUG);
}

__global__ __launch_bounds__(256) void oproj_gemm(const float* __restrict__ bo)
{
    int dir = blockIdx.z;
    gemm_body<false>(g_attb + (size_t)dir * MOUT * HID,
                     g_Wb + (size_t)3 * HID * HID, bo,
                     g_O + (size_t)dir * MOUT * HID, MOUT);
}

// ---------------------------------------------------------------------------
// Flash attention: register-resident P, 3-stage cp.async K/V pipeline.
// 8 warps x 16 q-rows; Bc=32 keys/iter; iters 0..63 unmasked, iter 64 masked.
// ---------------------------------------------------------------------------
__global__ __launch_bounds__(256, 2) void attn_bf16()
{
    __shared__ alignas(16) __nv_bfloat16 Kst[3][32][72];
    __shared__ alignas(16) __nv_bfloat16 Vst[3][32][72];

    const int tid  = threadIdx.x;
    const int lane = tid & 31;
    const int warp = tid >> 5;
    const int q = lane >> 2, r = lane & 3;
    const int g = lane >> 3, L = lane & 7;
    const int m0 = warp * 16;

    const int qt  = blockIdx.x;
    const int h   = blockIdx.y;
    const int dir = blockIdx.z >> 1;
    const int b   = blockIdx.z & 1;

    const __nv_bfloat16* qp =
        g_Qb + ((size_t)((dir * Bz + b) * SA) + qt * 128 + m0) * HID + h * HD;
    const size_t kvbase = ((size_t)(((dir ^ 1) * Bz + b) * SA)) * HID + h * HD;

    const uint32_t K_u = (uint32_t)__cvta_generic_to_shared(&Kst[0][0][0]);
    const uint32_t V_u = (uint32_t)__cvta_generic_to_shared(&Vst[0][0][0]);
    const int frow = tid >> 3, fseg = tid & 7;

    auto fill = [&](int t, int s) {
        const int key = t * 32 + frow;
        const bool ok = key < SA;
        const size_t off = kvbase + (size_t)(ok ? key : 0) * HID + fseg * 8;
        const uint32_t d = (uint32_t)(s * 32 * 72 + frow * 72 + fseg * 8) * 2;
        cpa16(K_u + d, g_Kb + off, ok);
        cpa16(V_u + d, g_Vb + off, ok);
    };

    // persistent Q fragments from gmem
    uint32_t aQ[4][4];
#pragma unroll
    for (int ks = 0; ks < 4; ks++) {
        const int c0 = ks * 16 + 2 * r;
        aQ[ks][0] = *(const uint32_t*)(qp + (size_t)q * HID + c0);
        aQ[ks][1] = *(const uint32_t*)(qp + (size_t)(q + 8) * HID + c0);
        aQ[ks][2] = *(const uint32_t*)(qp + (size_t)q * HID + c0 + 8);
        aQ[ks][3] = *(const uint32_t*)(qp + (size_t)(q + 8) * HID + c0 + 8);
    }

    float o[8][4];
#pragma unroll
    for (int i = 0; i < 8; i++)
#pragma unroll
        for (int j = 0; j < 4; j++) o[i][j] = 0.f;
    float l0 = 0.f, l1 = 0.f;

    fill(0, 0); CPA_COMMIT();
    fill(1, 1); CPA_COMMIT();

    int st = 0;
    for (int kt = 0; kt < 65; kt++) {
        CPA_WAIT1();
        __syncthreads();
        if (kt + 2 < 65) {
            int s2 = st + 2; if (s2 >= 3) s2 -= 3;
            fill(kt + 2, s2);
        }
        CPA_COMMIT();

        // ---- S = Q @ K^T (16 q x 32 keys per warp) ----
        float sAcc[4][4];
#pragma unroll
        for (int i = 0; i < 4; i++)
#pragma unroll
            for (int j = 0; j < 4; j++) sAcc[i][j] = 0.f;
#pragma unroll
        for (int ks = 0; ks < 4; ks++) {
            const int k0 = ks * 16;
            uint32_t bk_[4][2];
#pragma unroll
            for (int half = 0; half < 2; half++) {
                const int row = half * 16 + (g >> 1) * 8 + L;
                const int col = k0 + (g & 1) * 8;
                uint32_t r0, r1, r2, r3;
                ldsm4(r0, r1, r2, r3, &Kst[st][row][col]);
                bk_[half * 2][0] = r0; bk_[half * 2][1] = r1;
                bk_[half * 2 + 1][0] = r2; bk_[half * 2 + 1][1] = r3;
            }
#pragma unroll
            for (int nt = 0; nt < 4; nt++) mma_bf16(sAcc[nt], aQ[ks], bk_[nt]);
        }

        // ---- P = exp(S/8) in registers -> A fragments (no smem round trip) --
        float e[4][4];
        if (kt < 64) {
#pragma unroll
            for (int nt = 0; nt < 4; nt++) {
                e[nt][0] = __expf(sAcc[nt][0] * 0.125f);
                e[nt][1] = __expf(sAcc[nt][1] * 0.125f);
                e[nt][2] = __expf(sAcc[nt][2] * 0.125f);
                e[nt][3] = __expf(sAcc[nt][3] * 0.125f);
            }
        } else {
            const int kb = kt * 32;
#pragma unroll
            for (int nt = 0; nt < 4; nt++) {
                const int key0 = kb + nt * 8 + 2 * r;
                e[nt][0] = (key0     < SA) ? __expf(sAcc[nt][0] * 0.125f) : 0.f;
                e[nt][1] = (key0 + 1 < SA) ? __expf(sAcc[nt][1] * 0.125f) : 0.f;
                e[nt][2] = (key0     < SA) ? __expf(sAcc[nt][2] * 0.125f) : 0.f;
                e[nt][3] = (key0 + 1 < SA) ? __expf(sAcc[nt][3] * 0.125f) : 0.f;
            }
        }
#pragma unroll
        for (int nt = 0; nt < 4; nt++) {
            l0 += e[nt][0] + e[nt][1];
            l1 += e[nt][2] + e[nt][3];
        }
        uint32_t aP[2][4];
#pragma unroll
        for (int p = 0; p < 2; p++) {
            aP[p][0] = pk(e[2 * p][0],     e[2 * p][1]);
            aP[p][1] = pk(e[2 * p][2],     e[2 * p][3]);
            aP[p][2] = pk(e[2 * p + 1][0], e[2 * p + 1][1]);
            aP[p][3] = pk(e[2 * p + 1][2], e[2 * p + 1][3]);
        }

        // ---- O += P @ V ----
#pragma unroll
        for (int p = 0; p < 2; p++) {
            const int k0 = p * 16;
#pragma unroll
            for (int db = 0; db < 4; db++) {
                const int row = k0 + (g & 1) * 8 + L;
                const int col = db * 16 + (g >> 1) * 8;
                uint32_t r0, r1, r2, r3;
                ldsm4t(r0, r1, r2, r3, &Vst[st][row][col]);
                uint32_t b0[2] = {r0, r1};
                uint32_t b1[2] = {r2, r3};
                mma_bf16(o[db * 2], aP[p], b0);
                mma_bf16(o[db * 2 + 1], aP[p], b1);
            }
        }
        if (++st >= 3) st = 0;
    }

    l0 += __shfl_xor_sync(0xFFFFFFFFu, l0, 1);
    l0 += __shfl_xor_sync(0xFFFFFFFFu, l0, 2);
    l1 += __shfl_xor_sync(0xFFFFFFFFu, l1, 1);
    l1 += __shfl_xor_sync(0xFFFFFFFFu, l1, 2);
    const float inv0 = 1.0f / l0;
    const float inv1 = 1.0f / l1;

    __nv_bfloat16* op =
        g_attb + ((size_t)((dir * Bz + b) * SEQ) + qt * 128 + m0) * HID + h * HD;
#pragma unroll
    for (int nt2 = 0; nt2 < 8; nt2++) {
        const int c = nt2 * 8 + 2 * r;
        *(uint32_t*)(op + (size_t)q * HID + c) =
            pk(o[nt2][0] * inv0, o[nt2][1] * inv0);
        *(uint32_t*)(op + (size_t)(q + 8) * HID + c) =
            pk(o[nt2][2] * inv1, o[nt2][3] * inv1);
    }
}

// ---------------------------------------------------------------------------
// Kernel 4: residual + LayerNorm (fp32)
// ---------------------------------------------------------------------------
__global__ __launch_bounds__(256) void resid_ln(
    const float* __restrict__ cnn, const float* __restrict__ llm,
    const float* __restrict__ gamma, const float* __restrict__ beta,
    float* __restrict__ out)
{
    int row = blockIdx.x;
    int dir = row >> 12;
    int b   = (row >> 11) & 1;
    int s   = row & (SEQ - 1);
    const float* resid = (dir ? llm : cnn) + ((size_t)(b * SEQ + s)) * HID;
    const float* op = g_O + (size_t)row * HID;
    int t = threadIdx.x;

    float4 rv = *(const float4*)(resid + t * 4);
    float4 ov = *(const float4*)(op + t * 4);
    float x0 = rv.x + ov.x, x1 = rv.y + ov.y, x2 = rv.z + ov.z, x3 = rv.w + ov.w;
    float s1 = (x0 + x1) + (x2 + x3);
    float s2 = x0 * x0 + x1 * x1 + x2 * x2 + x3 * x3;
#pragma unroll
    for (int off = 16; off; off >>= 1) {
        s1 += __shfl_xor_sync(0xFFFFFFFFu, s1, off);
        s2 += __shfl_xor_sync(0xFFFFFFFFu, s2, off);
    }
    __shared__ float sm1[8], sm2[8];
    int wp = t >> 5, lane = t & 31;
    if (lane == 0) { sm1[wp] = s1; sm2[wp] = s2; }
    __syncthreads();
    if (t == 0) {
        float a = 0.f, c = 0.f;
#pragma unroll
        for (int i = 0; i < 8; i++) { a += sm1[i]; c += sm2[i]; }
        sm1[0] = a; sm2[0] = c;
    }
    __syncthreads();
    float mean = sm1[0] * (1.0f / HID);
    float var  = sm2[0] * (1.0f / HID) - mean * mean;
    float rstd = rsqrtf(var + 1e-5f);

    float4 gm = *(const float4*)(gamma + t * 4);
    float4 be = *(const float4*)(beta + t * 4);
    float4 y;
    y.x = (x0 - mean) * rstd * gm.x + be.x;
    y.y = (x1 - mean) * rstd * gm.y + be.y;
    y.z = (x2 - mean) * rstd * gm.z + be.z;
    y.w = (x3 - mean) * rstd * gm.w + be.w;
    *(float4*)(out + (size_t)row * HID + t * 4) = y;
}

// ---------------------------------------------------------------------------
extern "C" void kernel_launch(void* const* d_in, const int* in_sizes, int n_in,
                              void* d_out, int out_size)
{
    const float* cnn = (const float*)d_in[0];
    const float* llm = (const float*)d_in[1];
    const float* Wq  = (const float*)d_in[2];
    const float* bq  = (const float*)d_in[3];
    const float* Wk  = (const float*)d_in[4];
    const float* bk  = (const float*)d_in[5];
    const float* Wv  = (const float*)d_in[6];
    const float* bv  = (const float*)d_in[7];
    const float* Wo  = (const float*)d_in[8];
    const float* bo  = (const float*)d_in[9];
    const float* ee  = (const float*)d_in[10];
    const float* me  = (const float*)d_in[11];
    const float* pe  = (const float*)d_in[12];
    const float* gamma = (const float*)d_in[13];
    const float* beta  = (const float*)d_in[14];
    float* out = (float*)d_out;

    cudaFuncSetAttribute(qkv_gemm,
                         cudaFuncAttributeMaxDynamicSharedMemorySize, GEMM_SMEM);
    cudaFuncSetAttribute(oproj_gemm,
                         cudaFuncAttributeMaxDynamicSharedMemorySize, GEMM_SMEM);

    conv_w<<<4096, 256>>>(Wq, Wk, Wv, Wo);
    build_aug<<<2 * MAUG, 256>>>(cnn, llm, ee, me, pe);

    {   // QKV projections (6 GEMMs)
        dim3 grid(HID / 256, (MAUG + 127) / 128, 6);
        qkv_gemm<<<grid, 256, GEMM_SMEM>>>(bq, bk, bv);
    }
    {   // cross-attention, both directions
        dim3 grid(SEQ / 128, NHEADS, 2 * Bz);
        attn_bf16<<<grid, 256>>>();
    }
    {   // output projection (2 GEMMs)
        dim3 grid(HID / 256, MOUT / 128, 2);
        oproj_gemm<<<grid, 256, GEMM_SMEM>>>(bo);
    }
    resid_ln<<<2 * Bz * SEQ, 256>>>(cnn, llm, gamma, beta, out);
}